// round 1
// baseline (speedup 1.0000x reference)
#include <cuda_runtime.h>

#define N_NODES 55296
#define N_EDGES 221184
#define NB      110592   // BATCH * N_NODES

typedef unsigned long long ull;

// Scratch (static device arrays: no allocation at launch time)
__device__ float g_We[(size_t)N_EDGES * 1024];   // [E][h=32][o=32]
__device__ float g_hidden[(size_t)NB * 32];      // [b][n][32] flattened
__device__ float g_agg[(size_t)NB * 32];

// ---------- packed f32x2 helpers ----------
__device__ __forceinline__ ull pack2(float lo, float hi) {
    ull v; asm("mov.b64 %0, {%1, %2};" : "=l"(v) : "f"(lo), "f"(hi)); return v;
}
__device__ __forceinline__ float2 unpack2(ull v) {
    float2 f; asm("mov.b64 {%0, %1}, %2;" : "=f"(f.x), "=f"(f.y) : "l"(v)); return f;
}
__device__ __forceinline__ void fma2(ull& d, ull a, ull b) {
    asm("fma.rn.f32x2 %0, %1, %2, %0;" : "+l"(d) : "l"(a), "l"(b));
}
__device__ __forceinline__ float sigmoidf_(float x) {
    return __fdividef(1.f, 1.f + __expf(-x));
}

// ---------- node projection: h0 = ReLU(x@pw1+pb1)@pw2+pb2 ----------
__global__ void __launch_bounds__(128) proj_kernel(
    const float* __restrict__ x,
    const float* __restrict__ pw1, const float* __restrict__ pb1,
    const float* __restrict__ pw2, const float* __restrict__ pb2)
{
    __shared__ float s_w1[1024], s_w2[1024], s_b1[32], s_b2[32];
    int t = threadIdx.x;
    for (int i = t; i < 1024; i += 128) { s_w1[i] = pw1[i]; s_w2[i] = pw2[i]; }
    if (t < 32) { s_b1[t] = pb1[t]; s_b2[t] = pb2[t]; }
    __syncthreads();

    int idx = blockIdx.x * 128 + t;   // [0, NB)
    float v[32];
    const float4* xp = (const float4*)(x + (size_t)idx * 32);
    #pragma unroll
    for (int i = 0; i < 8; i++) {
        float4 xv = xp[i];
        v[4*i+0] = xv.x; v[4*i+1] = xv.y; v[4*i+2] = xv.z; v[4*i+3] = xv.w;
    }
    float4 acc[8];
    #pragma unroll
    for (int j = 0; j < 8; j++) acc[j] = ((const float4*)s_b1)[j];
    #pragma unroll
    for (int c = 0; c < 32; c++) {
        float xv = v[c];
        #pragma unroll
        for (int j = 0; j < 8; j++) {
            float4 w = ((const float4*)s_w1)[c*8 + j];
            acc[j].x = fmaf(xv, w.x, acc[j].x);
            acc[j].y = fmaf(xv, w.y, acc[j].y);
            acc[j].z = fmaf(xv, w.z, acc[j].z);
            acc[j].w = fmaf(xv, w.w, acc[j].w);
        }
    }
    #pragma unroll
    for (int j = 0; j < 8; j++) {
        v[4*j+0] = fmaxf(acc[j].x, 0.f);
        v[4*j+1] = fmaxf(acc[j].y, 0.f);
        v[4*j+2] = fmaxf(acc[j].z, 0.f);
        v[4*j+3] = fmaxf(acc[j].w, 0.f);
    }
    #pragma unroll
    for (int j = 0; j < 8; j++) acc[j] = ((const float4*)s_b2)[j];
    #pragma unroll
    for (int c = 0; c < 32; c++) {
        float xv = v[c];
        #pragma unroll
        for (int j = 0; j < 8; j++) {
            float4 w = ((const float4*)s_w2)[c*8 + j];
            acc[j].x = fmaf(xv, w.x, acc[j].x);
            acc[j].y = fmaf(xv, w.y, acc[j].y);
            acc[j].z = fmaf(xv, w.z, acc[j].z);
            acc[j].w = fmaf(xv, w.w, acc[j].w);
        }
    }
    float4* op = (float4*)(g_hidden + (size_t)idx * 32);
    #pragma unroll
    for (int j = 0; j < 8; j++) op[j] = acc[j];
}

// ---------- edge network GEMM: We = (ReLU(rel@ew1+eb1)) @ ew2 + eb2 ----------
// C[E,1024] = A[E,32] * B[32,1024].  Tile: 128 edges x 128 cols, 256 thr, 8x8 micro (f32x2)
__global__ void __launch_bounds__(256, 2) we_gemm_kernel(
    const float* __restrict__ rel,
    const float* __restrict__ ew1, const float* __restrict__ eb1,
    const float* __restrict__ ew2, const float* __restrict__ eb2)
{
    __shared__ float  s_a[32][128];   // [k][e]
    __shared__ float  s_b[32][128];   // [k][n]
    __shared__ float4 s_rel[128];
    __shared__ float  s_w1[128];
    __shared__ float  s_be[32];

    int t  = threadIdx.x;
    int e0 = blockIdx.y * 128;
    int n0 = blockIdx.x * 128;

    if (t < 128) { s_w1[t] = ew1[t]; s_rel[t] = ((const float4*)rel)[e0 + t]; }
    if (t >= 128 && t < 160) s_be[t - 128] = eb1[t - 128];
    __syncthreads();

    #pragma unroll
    for (int i = 0; i < 16; i++) {
        int idx = t + i * 256;
        int k = idx >> 7, e = idx & 127;
        float4 rp = s_rel[e];
        float a = s_be[k];
        a = fmaf(rp.x, s_w1[k],      a);
        a = fmaf(rp.y, s_w1[32 + k], a);
        a = fmaf(rp.z, s_w1[64 + k], a);
        a = fmaf(rp.w, s_w1[96 + k], a);
        s_a[k][e] = fmaxf(a, 0.f);
    }
    for (int i = t; i < 1024; i += 256) {
        int k = i >> 5, nq = i & 31;
        ((float4*)&s_b[k][0])[nq] = ((const float4*)(ew2 + (size_t)k * 1024 + n0))[nq];
    }
    __syncthreads();

    int tx = t & 15, ty = t >> 4;
    ull acc[8][4];
    #pragma unroll
    for (int i = 0; i < 8; i++)
        #pragma unroll
        for (int j = 0; j < 4; j++) acc[i][j] = 0ull;

    #pragma unroll
    for (int k = 0; k < 32; k++) {
        float4 a0 = *(const float4*)&s_a[k][ty * 8];
        float4 a1 = *(const float4*)&s_a[k][ty * 8 + 4];
        const ull* bp = (const ull*)&s_b[k][tx * 8];
        ull b0 = bp[0], b1 = bp[1], b2 = bp[2], b3 = bp[3];
        float av[8] = {a0.x, a0.y, a0.z, a0.w, a1.x, a1.y, a1.z, a1.w};
        #pragma unroll
        for (int i = 0; i < 8; i++) {
            ull ap = pack2(av[i], av[i]);
            fma2(acc[i][0], ap, b0); fma2(acc[i][1], ap, b1);
            fma2(acc[i][2], ap, b2); fma2(acc[i][3], ap, b3);
        }
    }

    float4 bias0 = *(const float4*)(eb2 + n0 + tx * 8);
    float4 bias1 = *(const float4*)(eb2 + n0 + tx * 8 + 4);
    #pragma unroll
    for (int i = 0; i < 8; i++) {
        size_t row = (size_t)(e0 + ty * 8 + i);
        float* cp = g_We + row * 1024 + n0 + tx * 8;
        float2 c0 = unpack2(acc[i][0]), c1 = unpack2(acc[i][1]);
        float2 c2 = unpack2(acc[i][2]), c3 = unpack2(acc[i][3]);
        float4 o0 = make_float4(c0.x + bias0.x, c0.y + bias0.y, c1.x + bias0.z, c1.y + bias0.w);
        float4 o1 = make_float4(c2.x + bias1.x, c2.y + bias1.y, c3.x + bias1.z, c3.y + bias1.w);
        __stcs((float4*)cp, o0);
        __stcs((float4*)cp + 1, o1);
    }
}

// ---------- agg = conv_b (broadcast init) ----------
__global__ void init_agg_kernel(const float* __restrict__ conv_b)
{
    int i = blockIdx.x * 256 + threadIdx.x;        // float4 index, total NB*8
    float4 v = __ldg(((const float4*)conv_b) + (i & 7));
    ((float4*)g_agg)[i] = v;
}

// ---------- message + scatter: agg[b,dst] += node[b,src] @ We[e] ----------
// 8 lanes per edge, 4 edges per warp. Streams We with __ldcs (evict-first).
__global__ void __launch_bounds__(256) msg_kernel(
    const int* __restrict__ esrc, const int* __restrict__ edst)
{
    int gtid = blockIdx.x * 256 + threadIdx.x;
    int warp = gtid >> 5;
    int lane = threadIdx.x & 31;
    int g = lane >> 3, q = lane & 7;
    int e = warp * 4 + g;

    int s = esrc[e], d = edst[e];
    const float4* np = (const float4*)g_hidden + (size_t)s * 8 + q;
    float4 v0 = __ldg(np);
    float4 v1 = __ldg(np + (size_t)N_NODES * 8);

    const float4* wp = (const float4*)(g_We + (size_t)e * 1024) + q;
    float4 acc0 = make_float4(0.f, 0.f, 0.f, 0.f);
    float4 acc1 = make_float4(0.f, 0.f, 0.f, 0.f);

    #pragma unroll
    for (int h = 0; h < 32; h++) {
        float4 w = __ldcs(wp + h * 8);
        int hq = h >> 2, rc = h & 3;
        float c0 = (rc == 0) ? v0.x : (rc == 1) ? v0.y : (rc == 2) ? v0.z : v0.w;
        float c1 = (rc == 0) ? v1.x : (rc == 1) ? v1.y : (rc == 2) ? v1.z : v1.w;
        float n0 = __shfl_sync(0xffffffffu, c0, hq, 8);
        float n1 = __shfl_sync(0xffffffffu, c1, hq, 8);
        acc0.x = fmaf(n0, w.x, acc0.x); acc0.y = fmaf(n0, w.y, acc0.y);
        acc0.z = fmaf(n0, w.z, acc0.z); acc0.w = fmaf(n0, w.w, acc0.w);
        acc1.x = fmaf(n1, w.x, acc1.x); acc1.y = fmaf(n1, w.y, acc1.y);
        acc1.z = fmaf(n1, w.z, acc1.z); acc1.w = fmaf(n1, w.w, acc1.w);
    }
    float* ap0 = g_agg + (size_t)d * 32 + q * 4;
    atomicAdd(ap0 + 0, acc0.x); atomicAdd(ap0 + 1, acc0.y);
    atomicAdd(ap0 + 2, acc0.z); atomicAdd(ap0 + 3, acc0.w);
    float* ap1 = ap0 + (size_t)N_NODES * 32;
    atomicAdd(ap1 + 0, acc1.x); atomicAdd(ap1 + 1, acc1.y);
    atomicAdd(ap1 + 2, acc1.z); atomicAdd(ap1 + 3, acc1.w);
}

// ---------- fused ReLU + GRU cell ----------
__global__ void __launch_bounds__(128) gru_kernel(
    const float* __restrict__ wih, const float* __restrict__ whh,
    const float* __restrict__ bih, const float* __restrict__ bhh,
    float* __restrict__ d_out, int last)
{
    __shared__ float s_wih[3072], s_whh[3072];
    __shared__ float s_bih[96], s_bhh[96];
    __shared__ float s_h[128][33];

    int t = threadIdx.x;
    for (int i = t; i < 3072; i += 128) { s_wih[i] = wih[i]; s_whh[i] = whh[i]; }
    if (t < 96) { s_bih[t] = bih[t]; s_bhh[t] = bhh[t]; }

    int idx = blockIdx.x * 128 + t;   // [0, NB)
    ull a2[16], h2[16];
    const float4* ap = (const float4*)(g_agg + (size_t)idx * 32);
    const float4* hp = (const float4*)(g_hidden + (size_t)idx * 32);
    #pragma unroll
    for (int i = 0; i < 8; i++) {
        float4 av = ap[i];
        av.x = fmaxf(av.x, 0.f); av.y = fmaxf(av.y, 0.f);
        av.z = fmaxf(av.z, 0.f); av.w = fmaxf(av.w, 0.f);
        a2[2*i]   = pack2(av.x, av.y);
        a2[2*i+1] = pack2(av.z, av.w);
        float4 hv = hp[i];
        h2[2*i]   = pack2(hv.x, hv.y);
        h2[2*i+1] = pack2(hv.z, hv.w);
        s_h[t][4*i+0] = hv.x; s_h[t][4*i+1] = hv.y;
        s_h[t][4*i+2] = hv.z; s_h[t][4*i+3] = hv.w;
    }
    __syncthreads();

    float* outp = last ? (d_out + (size_t)idx * 32) : (g_hidden + (size_t)idx * 32);

    for (int l = 0; l < 32; l++) {
        ull rx = 0, rh = 0, zx = 0, zh = 0, nx = 0, nh = 0;
        const ull* wr = (const ull*)(s_wih + l * 32);
        const ull* wz = (const ull*)(s_wih + (32 + l) * 32);
        const ull* wn = (const ull*)(s_wih + (64 + l) * 32);
        const ull* ur = (const ull*)(s_whh + l * 32);
        const ull* uz = (const ull*)(s_whh + (32 + l) * 32);
        const ull* un = (const ull*)(s_whh + (64 + l) * 32);
        #pragma unroll
        for (int q = 0; q < 16; q++) {
            fma2(rx, a2[q], wr[q]); fma2(rh, h2[q], ur[q]);
            fma2(zx, a2[q], wz[q]); fma2(zh, h2[q], uz[q]);
            fma2(nx, a2[q], wn[q]); fma2(nh, h2[q], un[q]);
        }
        float2 frx = unpack2(rx), frh = unpack2(rh);
        float rv = sigmoidf_(frx.x + frx.y + frh.x + frh.y + s_bih[l] + s_bhh[l]);
        float2 fzx = unpack2(zx), fzh = unpack2(zh);
        float zv = sigmoidf_(fzx.x + fzx.y + fzh.x + fzh.y + s_bih[32 + l] + s_bhh[32 + l]);
        float2 fnx = unpack2(nx), fnh = unpack2(nh);
        float gxn = fnx.x + fnx.y + s_bih[64 + l];
        float ghn = fnh.x + fnh.y + s_bhh[64 + l];
        float nv = tanhf(fmaf(rv, ghn, gxn));
        float hold = s_h[t][l];
        s_h[t][l] = (1.f - zv) * nv + zv * hold;
    }

    #pragma unroll
    for (int i = 0; i < 8; i++) {
        float4 o;
        o.x = s_h[t][4*i+0]; o.y = s_h[t][4*i+1];
        o.z = s_h[t][4*i+2]; o.w = s_h[t][4*i+3];
        ((float4*)outp)[i] = o;
    }
}

extern "C" void kernel_launch(void* const* d_in, const int* in_sizes, int n_in,
                              void* d_out, int out_size)
{
    const float* x     = (const float*)d_in[0];
    const float* rel   = (const float*)d_in[1];
    const float* pw1   = (const float*)d_in[2];
    const float* pb1   = (const float*)d_in[3];
    const float* pw2   = (const float*)d_in[4];
    const float* pb2   = (const float*)d_in[5];
    const float* ew1   = (const float*)d_in[6];
    const float* eb1   = (const float*)d_in[7];
    const float* ew2   = (const float*)d_in[8];
    const float* eb2   = (const float*)d_in[9];
    const float* convb = (const float*)d_in[10];
    const float* wih   = (const float*)d_in[11];
    const float* whh   = (const float*)d_in[12];
    const float* bih   = (const float*)d_in[13];
    const float* bhh   = (const float*)d_in[14];
    const int*   esrc  = (const int*)d_in[15];
    const int*   edst  = (const int*)d_in[16];
    float* out = (float*)d_out;

    proj_kernel<<<NB / 128, 128>>>(x, pw1, pb1, pw2, pb2);
    we_gemm_kernel<<<dim3(8, N_EDGES / 128), 256>>>(rel, ew1, eb1, ew2, eb2);

    for (int s = 0; s < 3; s++) {
        init_agg_kernel<<<(NB * 8) / 256, 256>>>(convb);
        msg_kernel<<<N_EDGES / 32, 256>>>(esrc, edst);   // 4 edges/warp, 8 warps/block
        gru_kernel<<<NB / 128, 128>>>(wih, whh, bih, bhh, out, s == 2 ? 1 : 0);
    }
}

// round 2
// speedup vs baseline: 1.3294x; 1.3294x over previous
#include <cuda_runtime.h>
#include <cuda_fp16.h>

#define N_NODES 55296
#define N_EDGES 221184
#define NB      110592   // BATCH * N_NODES

typedef unsigned long long ull;

// Scratch (static device arrays: no allocation at launch time)
__device__ __half g_We[(size_t)N_EDGES * 1024];  // [E][h=32][o=32] fp16
__device__ float g_hidden[(size_t)NB * 32];      // [b][n][32] flattened
__device__ float g_agg[(size_t)NB * 32];

// ---------- packed f32x2 helpers ----------
__device__ __forceinline__ ull pack2(float lo, float hi) {
    ull v; asm("mov.b64 %0, {%1, %2};" : "=l"(v) : "f"(lo), "f"(hi)); return v;
}
__device__ __forceinline__ float2 unpack2(ull v) {
    float2 f; asm("mov.b64 {%0, %1}, %2;" : "=f"(f.x), "=f"(f.y) : "l"(v)); return f;
}
__device__ __forceinline__ void fma2(ull& d, ull a, ull b) {
    asm("fma.rn.f32x2 %0, %1, %2, %0;" : "+l"(d) : "l"(a), "l"(b));
}
__device__ __forceinline__ float sigmoidf_(float x) {
    return __fdividef(1.f, 1.f + __expf(-x));
}

// ---------- node projection: h0 = ReLU(x@pw1+pb1)@pw2+pb2 ----------
__global__ void __launch_bounds__(128) proj_kernel(
    const float* __restrict__ x,
    const float* __restrict__ pw1, const float* __restrict__ pb1,
    const float* __restrict__ pw2, const float* __restrict__ pb2)
{
    __shared__ float s_w1[1024], s_w2[1024], s_b1[32], s_b2[32];
    int t = threadIdx.x;
    for (int i = t; i < 1024; i += 128) { s_w1[i] = pw1[i]; s_w2[i] = pw2[i]; }
    if (t < 32) { s_b1[t] = pb1[t]; s_b2[t] = pb2[t]; }
    __syncthreads();

    int idx = blockIdx.x * 128 + t;   // [0, NB)
    float v[32];
    const float4* xp = (const float4*)(x + (size_t)idx * 32);
    #pragma unroll
    for (int i = 0; i < 8; i++) {
        float4 xv = xp[i];
        v[4*i+0] = xv.x; v[4*i+1] = xv.y; v[4*i+2] = xv.z; v[4*i+3] = xv.w;
    }
    float4 acc[8];
    #pragma unroll
    for (int j = 0; j < 8; j++) acc[j] = ((const float4*)s_b1)[j];
    #pragma unroll
    for (int c = 0; c < 32; c++) {
        float xv = v[c];
        #pragma unroll
        for (int j = 0; j < 8; j++) {
            float4 w = ((const float4*)s_w1)[c*8 + j];
            acc[j].x = fmaf(xv, w.x, acc[j].x);
            acc[j].y = fmaf(xv, w.y, acc[j].y);
            acc[j].z = fmaf(xv, w.z, acc[j].z);
            acc[j].w = fmaf(xv, w.w, acc[j].w);
        }
    }
    #pragma unroll
    for (int j = 0; j < 8; j++) {
        v[4*j+0] = fmaxf(acc[j].x, 0.f);
        v[4*j+1] = fmaxf(acc[j].y, 0.f);
        v[4*j+2] = fmaxf(acc[j].z, 0.f);
        v[4*j+3] = fmaxf(acc[j].w, 0.f);
    }
    #pragma unroll
    for (int j = 0; j < 8; j++) acc[j] = ((const float4*)s_b2)[j];
    #pragma unroll
    for (int c = 0; c < 32; c++) {
        float xv = v[c];
        #pragma unroll
        for (int j = 0; j < 8; j++) {
            float4 w = ((const float4*)s_w2)[c*8 + j];
            acc[j].x = fmaf(xv, w.x, acc[j].x);
            acc[j].y = fmaf(xv, w.y, acc[j].y);
            acc[j].z = fmaf(xv, w.z, acc[j].z);
            acc[j].w = fmaf(xv, w.w, acc[j].w);
        }
    }
    float4* op = (float4*)(g_hidden + (size_t)idx * 32);
    #pragma unroll
    for (int j = 0; j < 8; j++) op[j] = acc[j];
}

// ---------- edge network GEMM: We = (ReLU(rel@ew1+eb1)) @ ew2 + eb2, fp16 out ----------
// C[E,1024] = A[E,32] * B[32,1024].  Tile: 128 edges x 128 cols, 256 thr, 8x8 micro (f32x2)
__global__ void __launch_bounds__(256, 2) we_gemm_kernel(
    const float* __restrict__ rel,
    const float* __restrict__ ew1, const float* __restrict__ eb1,
    const float* __restrict__ ew2, const float* __restrict__ eb2)
{
    __shared__ float  s_a[32][128];   // [k][e]
    __shared__ float  s_b[32][128];   // [k][n]
    __shared__ float4 s_rel[128];
    __shared__ float  s_w1[128];
    __shared__ float  s_be[32];

    int t  = threadIdx.x;
    int e0 = blockIdx.y * 128;
    int n0 = blockIdx.x * 128;

    if (t < 128) { s_w1[t] = ew1[t]; s_rel[t] = ((const float4*)rel)[e0 + t]; }
    if (t >= 128 && t < 160) s_be[t - 128] = eb1[t - 128];
    __syncthreads();

    #pragma unroll
    for (int i = 0; i < 16; i++) {
        int idx = t + i * 256;
        int k = idx >> 7, e = idx & 127;
        float4 rp = s_rel[e];
        float a = s_be[k];
        a = fmaf(rp.x, s_w1[k],      a);
        a = fmaf(rp.y, s_w1[32 + k], a);
        a = fmaf(rp.z, s_w1[64 + k], a);
        a = fmaf(rp.w, s_w1[96 + k], a);
        s_a[k][e] = fmaxf(a, 0.f);
    }
    for (int i = t; i < 1024; i += 256) {
        int k = i >> 5, nq = i & 31;
        ((float4*)&s_b[k][0])[nq] = ((const float4*)(ew2 + (size_t)k * 1024 + n0))[nq];
    }
    __syncthreads();

    int tx = t & 15, ty = t >> 4;
    ull acc[8][4];
    #pragma unroll
    for (int i = 0; i < 8; i++)
        #pragma unroll
        for (int j = 0; j < 4; j++) acc[i][j] = 0ull;

    #pragma unroll
    for (int k = 0; k < 32; k++) {
        float4 a0 = *(const float4*)&s_a[k][ty * 8];
        float4 a1 = *(const float4*)&s_a[k][ty * 8 + 4];
        const ull* bp = (const ull*)&s_b[k][tx * 8];
        ull b0 = bp[0], b1 = bp[1], b2 = bp[2], b3 = bp[3];
        float av[8] = {a0.x, a0.y, a0.z, a0.w, a1.x, a1.y, a1.z, a1.w};
        #pragma unroll
        for (int i = 0; i < 8; i++) {
            ull ap = pack2(av[i], av[i]);
            fma2(acc[i][0], ap, b0); fma2(acc[i][1], ap, b1);
            fma2(acc[i][2], ap, b2); fma2(acc[i][3], ap, b3);
        }
    }

    float4 bias0 = *(const float4*)(eb2 + n0 + tx * 8);
    float4 bias1 = *(const float4*)(eb2 + n0 + tx * 8 + 4);
    #pragma unroll
    for (int i = 0; i < 8; i++) {
        size_t row = (size_t)(e0 + ty * 8 + i);
        __half* cp = g_We + row * 1024 + n0 + tx * 8;
        float2 c0 = unpack2(acc[i][0]), c1 = unpack2(acc[i][1]);
        float2 c2 = unpack2(acc[i][2]), c3 = unpack2(acc[i][3]);
        __half2 p0 = __floats2half2_rn(c0.x + bias0.x, c0.y + bias0.y);
        __half2 p1 = __floats2half2_rn(c1.x + bias0.z, c1.y + bias0.w);
        __half2 p2 = __floats2half2_rn(c2.x + bias1.x, c2.y + bias1.y);
        __half2 p3 = __floats2half2_rn(c3.x + bias1.z, c3.y + bias1.w);
        uint4 packed;
        packed.x = *(unsigned int*)&p0; packed.y = *(unsigned int*)&p1;
        packed.z = *(unsigned int*)&p2; packed.w = *(unsigned int*)&p3;
        __stcs((uint4*)cp, packed);
    }
}

// ---------- agg = conv_b (broadcast init) ----------
__global__ void init_agg_kernel(const float* __restrict__ conv_b)
{
    int i = blockIdx.x * 256 + threadIdx.x;        // float4 index, total NB*8
    float4 v = __ldg(((const float4*)conv_b) + (i & 7));
    ((float4*)g_agg)[i] = v;
}

// ---------- message + scatter: agg[b,dst] += node[b,src] @ We[e] ----------
// 8 lanes per edge, 4 edges per warp. Streams fp16 We with __ldcs (evict-first).
__global__ void __launch_bounds__(256) msg_kernel(
    const int* __restrict__ esrc, const int* __restrict__ edst)
{
    int gtid = blockIdx.x * 256 + threadIdx.x;
    int warp = gtid >> 5;
    int lane = threadIdx.x & 31;
    int g = lane >> 3, q = lane & 7;
    int e = warp * 4 + g;

    int s = esrc[e], d = edst[e];
    const float4* np = (const float4*)g_hidden + (size_t)s * 8 + q;
    float4 v0 = __ldg(np);
    float4 v1 = __ldg(np + (size_t)N_NODES * 8);

    const __half* wp = g_We + (size_t)e * 1024 + q * 4;
    float4 acc0 = make_float4(0.f, 0.f, 0.f, 0.f);
    float4 acc1 = make_float4(0.f, 0.f, 0.f, 0.f);

    #pragma unroll
    for (int h = 0; h < 32; h++) {
        uint2 wraw = __ldcs((const uint2*)(wp + h * 32));
        float2 w01 = __half22float2(*(__half2*)&wraw.x);
        float2 w23 = __half22float2(*(__half2*)&wraw.y);
        int hq = h >> 2, rc = h & 3;
        float c0 = (rc == 0) ? v0.x : (rc == 1) ? v0.y : (rc == 2) ? v0.z : v0.w;
        float c1 = (rc == 0) ? v1.x : (rc == 1) ? v1.y : (rc == 2) ? v1.z : v1.w;
        float n0 = __shfl_sync(0xffffffffu, c0, hq, 8);
        float n1 = __shfl_sync(0xffffffffu, c1, hq, 8);
        acc0.x = fmaf(n0, w01.x, acc0.x); acc0.y = fmaf(n0, w01.y, acc0.y);
        acc0.z = fmaf(n0, w23.x, acc0.z); acc0.w = fmaf(n0, w23.y, acc0.w);
        acc1.x = fmaf(n1, w01.x, acc1.x); acc1.y = fmaf(n1, w01.y, acc1.y);
        acc1.z = fmaf(n1, w23.x, acc1.z); acc1.w = fmaf(n1, w23.y, acc1.w);
    }
    float* ap0 = g_agg + (size_t)d * 32 + q * 4;
    atomicAdd(ap0 + 0, acc0.x); atomicAdd(ap0 + 1, acc0.y);
    atomicAdd(ap0 + 2, acc0.z); atomicAdd(ap0 + 3, acc0.w);
    float* ap1 = ap0 + (size_t)N_NODES * 32;
    atomicAdd(ap1 + 0, acc1.x); atomicAdd(ap1 + 1, acc1.y);
    atomicAdd(ap1 + 2, acc1.z); atomicAdd(ap1 + 3, acc1.w);
}

// ---------- fused ReLU + GRU cell ----------
__global__ void __launch_bounds__(128) gru_kernel(
    const float* __restrict__ wih, const float* __restrict__ whh,
    const float* __restrict__ bih, const float* __restrict__ bhh,
    float* __restrict__ d_out, int last)
{
    __shared__ float s_wih[3072], s_whh[3072];
    __shared__ float s_bih[96], s_bhh[96];
    __shared__ float s_h[128][33];

    int t = threadIdx.x;
    for (int i = t; i < 3072; i += 128) { s_wih[i] = wih[i]; s_whh[i] = whh[i]; }
    if (t < 96) { s_bih[t] = bih[t]; s_bhh[t] = bhh[t]; }

    int idx = blockIdx.x * 128 + t;   // [0, NB)
    ull a2[16], h2[16];
    const float4* ap = (const float4*)(g_agg + (size_t)idx * 32);
    const float4* hp = (const float4*)(g_hidden + (size_t)idx * 32);
    #pragma unroll
    for (int i = 0; i < 8; i++) {
        float4 av = ap[i];
        av.x = fmaxf(av.x, 0.f); av.y = fmaxf(av.y, 0.f);
        av.z = fmaxf(av.z, 0.f); av.w = fmaxf(av.w, 0.f);
        a2[2*i]   = pack2(av.x, av.y);
        a2[2*i+1] = pack2(av.z, av.w);
        float4 hv = hp[i];
        h2[2*i]   = pack2(hv.x, hv.y);
        h2[2*i+1] = pack2(hv.z, hv.w);
        s_h[t][4*i+0] = hv.x; s_h[t][4*i+1] = hv.y;
        s_h[t][4*i+2] = hv.z; s_h[t][4*i+3] = hv.w;
    }
    __syncthreads();

    float* outp = last ? (d_out + (size_t)idx * 32) : (g_hidden + (size_t)idx * 32);

    for (int l = 0; l < 32; l++) {
        ull rx = 0, rh = 0, zx = 0, zh = 0, nx = 0, nh = 0;
        const ull* wr = (const ull*)(s_wih + l * 32);
        const ull* wz = (const ull*)(s_wih + (32 + l) * 32);
        const ull* wn = (const ull*)(s_wih + (64 + l) * 32);
        const ull* ur = (const ull*)(s_whh + l * 32);
        const ull* uz = (const ull*)(s_whh + (32 + l) * 32);
        const ull* un = (const ull*)(s_whh + (64 + l) * 32);
        #pragma unroll
        for (int q = 0; q < 16; q++) {
            fma2(rx, a2[q], wr[q]); fma2(rh, h2[q], ur[q]);
            fma2(zx, a2[q], wz[q]); fma2(zh, h2[q], uz[q]);
            fma2(nx, a2[q], wn[q]); fma2(nh, h2[q], un[q]);
        }
        float2 frx = unpack2(rx), frh = unpack2(rh);
        float rv = sigmoidf_(frx.x + frx.y + frh.x + frh.y + s_bih[l] + s_bhh[l]);
        float2 fzx = unpack2(zx), fzh = unpack2(zh);
        float zv = sigmoidf_(fzx.x + fzx.y + fzh.x + fzh.y + s_bih[32 + l] + s_bhh[32 + l]);
        float2 fnx = unpack2(nx), fnh = unpack2(nh);
        float gxn = fnx.x + fnx.y + s_bih[64 + l];
        float ghn = fnh.x + fnh.y + s_bhh[64 + l];
        float nv = tanhf(fmaf(rv, ghn, gxn));
        float hold = s_h[t][l];
        s_h[t][l] = (1.f - zv) * nv + zv * hold;
    }

    #pragma unroll
    for (int i = 0; i < 8; i++) {
        float4 o;
        o.x = s_h[t][4*i+0]; o.y = s_h[t][4*i+1];
        o.z = s_h[t][4*i+2]; o.w = s_h[t][4*i+3];
        ((float4*)outp)[i] = o;
    }
}

extern "C" void kernel_launch(void* const* d_in, const int* in_sizes, int n_in,
                              void* d_out, int out_size)
{
    const float* x     = (const float*)d_in[0];
    const float* rel   = (const float*)d_in[1];
    const float* pw1   = (const float*)d_in[2];
    const float* pb1   = (const float*)d_in[3];
    const float* pw2   = (const float*)d_in[4];
    const float* pb2   = (const float*)d_in[5];
    const float* ew1   = (const float*)d_in[6];
    const float* eb1   = (const float*)d_in[7];
    const float* ew2   = (const float*)d_in[8];
    const float* eb2   = (const float*)d_in[9];
    const float* convb = (const float*)d_in[10];
    const float* wih   = (const float*)d_in[11];
    const float* whh   = (const float*)d_in[12];
    const float* bih   = (const float*)d_in[13];
    const float* bhh   = (const float*)d_in[14];
    const int*   esrc  = (const int*)d_in[15];
    const int*   edst  = (const int*)d_in[16];
    float* out = (float*)d_out;

    proj_kernel<<<NB / 128, 128>>>(x, pw1, pb1, pw2, pb2);
    we_gemm_kernel<<<dim3(8, N_EDGES / 128), 256>>>(rel, ew1, eb1, ew2, eb2);

    for (int s = 0; s < 3; s++) {
        init_agg_kernel<<<(NB * 8) / 256, 256>>>(convb);
        msg_kernel<<<N_EDGES / 32, 256>>>(esrc, edst);   // 4 edges/warp, 8 warps/block
        gru_kernel<<<NB / 128, 128>>>(wih, whh, bih, bhh, out, s == 2 ? 1 : 0);
    }
}

// round 3
// speedup vs baseline: 1.4774x; 1.1113x over previous
#include <cuda_runtime.h>
#include <cuda_fp16.h>

#define N_NODES 55296
#define N_EDGES 221184
#define NB      110592   // BATCH * N_NODES

typedef unsigned long long ull;

// Scratch (static device arrays: no allocation at launch time)
__device__ __half g_We[(size_t)N_EDGES * 1024];  // [E][h=32][o=32] fp16
__device__ __half g_bt[1024 * 32];               // ew2 transposed: [n][k] fp16
__device__ float g_hidden[(size_t)NB * 32];      // [b][n][32] flattened
__device__ float g_agg[(size_t)NB * 32];

// ---------- packed f32x2 helpers ----------
__device__ __forceinline__ ull pack2(float lo, float hi) {
    ull v; asm("mov.b64 %0, {%1, %2};" : "=l"(v) : "f"(lo), "f"(hi)); return v;
}
__device__ __forceinline__ float2 unpack2(ull v) {
    float2 f; asm("mov.b64 {%0, %1}, %2;" : "=f"(f.x), "=f"(f.y) : "l"(v)); return f;
}
__device__ __forceinline__ void fma2(ull& d, ull a, ull b) {
    asm("fma.rn.f32x2 %0, %1, %2, %0;" : "+l"(d) : "l"(a), "l"(b));
}
__device__ __forceinline__ float sigmoidf_(float x) {
    return __fdividef(1.f, 1.f + __expf(-x));
}

// ---------- node projection: h0 = ReLU(x@pw1+pb1)@pw2+pb2 ; also zero g_agg ----------
__global__ void __launch_bounds__(128) proj_kernel(
    const float* __restrict__ x,
    const float* __restrict__ pw1, const float* __restrict__ pb1,
    const float* __restrict__ pw2, const float* __restrict__ pb2)
{
    __shared__ float s_w1[1024], s_w2[1024], s_b1[32], s_b2[32];
    int t = threadIdx.x;
    for (int i = t; i < 1024; i += 128) { s_w1[i] = pw1[i]; s_w2[i] = pw2[i]; }
    if (t < 32) { s_b1[t] = pb1[t]; s_b2[t] = pb2[t]; }
    __syncthreads();

    int idx = blockIdx.x * 128 + t;   // [0, NB)

    // zero agg for the first msg pass
    float4 z = make_float4(0.f, 0.f, 0.f, 0.f);
    float4* zp = (float4*)(g_agg + (size_t)idx * 32);
    #pragma unroll
    for (int j = 0; j < 8; j++) zp[j] = z;

    float v[32];
    const float4* xp = (const float4*)(x + (size_t)idx * 32);
    #pragma unroll
    for (int i = 0; i < 8; i++) {
        float4 xv = xp[i];
        v[4*i+0] = xv.x; v[4*i+1] = xv.y; v[4*i+2] = xv.z; v[4*i+3] = xv.w;
    }
    float4 acc[8];
    #pragma unroll
    for (int j = 0; j < 8; j++) acc[j] = ((const float4*)s_b1)[j];
    #pragma unroll
    for (int c = 0; c < 32; c++) {
        float xv = v[c];
        #pragma unroll
        for (int j = 0; j < 8; j++) {
            float4 w = ((const float4*)s_w1)[c*8 + j];
            acc[j].x = fmaf(xv, w.x, acc[j].x);
            acc[j].y = fmaf(xv, w.y, acc[j].y);
            acc[j].z = fmaf(xv, w.z, acc[j].z);
            acc[j].w = fmaf(xv, w.w, acc[j].w);
        }
    }
    #pragma unroll
    for (int j = 0; j < 8; j++) {
        v[4*j+0] = fmaxf(acc[j].x, 0.f);
        v[4*j+1] = fmaxf(acc[j].y, 0.f);
        v[4*j+2] = fmaxf(acc[j].z, 0.f);
        v[4*j+3] = fmaxf(acc[j].w, 0.f);
    }
    #pragma unroll
    for (int j = 0; j < 8; j++) acc[j] = ((const float4*)s_b2)[j];
    #pragma unroll
    for (int c = 0; c < 32; c++) {
        float xv = v[c];
        #pragma unroll
        for (int j = 0; j < 8; j++) {
            float4 w = ((const float4*)s_w2)[c*8 + j];
            acc[j].x = fmaf(xv, w.x, acc[j].x);
            acc[j].y = fmaf(xv, w.y, acc[j].y);
            acc[j].z = fmaf(xv, w.z, acc[j].z);
            acc[j].w = fmaf(xv, w.w, acc[j].w);
        }
    }
    float4* op = (float4*)(g_hidden + (size_t)idx * 32);
    #pragma unroll
    for (int j = 0; j < 8; j++) op[j] = acc[j];
}

// ---------- prep: g_bt[n][k] = (half)ew2[k][n] ----------
__global__ void bt_prep_kernel(const float* __restrict__ ew2)
{
    int i = blockIdx.x * 256 + threadIdx.x;   // [0, 32768)
    int k = i >> 10, n = i & 1023;
    g_bt[n * 32 + k] = __float2half(ew2[i]);
}

// ---------- edge network GEMM via tensor cores ----------
// C[E,1024] = A[E,32] * B[32,1024], A = ReLU(rel@ew1+eb1), fp16 in, fp32 acc, fp16 out
// Tile: 128 edges x 128 cols, 256 thr (8 warps), each warp: 16 edges x 128 cols
__global__ void __launch_bounds__(256, 2) we_gemm_kernel(
    const float* __restrict__ rel,
    const float* __restrict__ ew1, const float* __restrict__ eb1,
    const float* __restrict__ eb2)
{
    __shared__ __half s_a[128 * 40];    // [e][k], stride 40 (conflict-free frags)
    __shared__ __half s_bt[128 * 40];   // [n][k], stride 40
    __shared__ float4 s_rel[128];
    __shared__ float  s_w1[128];
    __shared__ float  s_be[32];
    __shared__ float  s_bias[128];

    int t  = threadIdx.x;
    int e0 = blockIdx.y * 128;
    int n0 = blockIdx.x * 128;

    if (t < 128) {
        s_w1[t] = ew1[t];
        s_rel[t] = ((const float4*)rel)[e0 + t];
        s_bias[t] = eb2[n0 + t];
    }
    if (t >= 128 && t < 160) s_be[t - 128] = eb1[t - 128];
    __syncthreads();

    // A prep: ReLU(rel@ew1+eb1) -> half, [e][k]
    #pragma unroll
    for (int i = 0; i < 16; i++) {
        int idx = t + i * 256;
        int k = idx >> 7, e = idx & 127;
        float4 rp = s_rel[e];
        float a = s_be[k];
        a = fmaf(rp.x, s_w1[k],      a);
        a = fmaf(rp.y, s_w1[32 + k], a);
        a = fmaf(rp.z, s_w1[64 + k], a);
        a = fmaf(rp.w, s_w1[96 + k], a);
        s_a[e * 40 + k] = __float2half(fmaxf(a, 0.f));
    }
    // B tile: copy 128 rows of g_bt (32 halves each) into padded smem
    {
        const uint4* src = (const uint4*)(g_bt + (size_t)n0 * 32);
        for (int j = t; j < 512; j += 256) {
            int n = j >> 2, p = j & 3;
            *(uint4*)(s_bt + n * 40 + p * 8) = src[j];
        }
    }
    __syncthreads();

    int w = t >> 5, lane = t & 31;
    int g = lane >> 2, tg = lane & 3;
    int erow = w * 16;

    // A fragments: 2 k-steps of m16k16
    unsigned af[2][4];
    #pragma unroll
    for (int s = 0; s < 2; s++) {
        const __half* ar0 = s_a + (erow + g) * 40 + s * 16 + tg * 2;
        const __half* ar1 = s_a + (erow + g + 8) * 40 + s * 16 + tg * 2;
        af[s][0] = *(const unsigned*)(ar0);
        af[s][1] = *(const unsigned*)(ar1);
        af[s][2] = *(const unsigned*)(ar0 + 8);
        af[s][3] = *(const unsigned*)(ar1 + 8);
    }

    float c[16][4];
    #pragma unroll
    for (int nt = 0; nt < 16; nt++)
        #pragma unroll
        for (int j = 0; j < 4; j++) c[nt][j] = 0.f;

    #pragma unroll
    for (int nt = 0; nt < 16; nt++) {
        #pragma unroll
        for (int s = 0; s < 2; s++) {
            const __half* br = s_bt + (nt * 8 + g) * 40 + s * 16 + tg * 2;
            unsigned b0 = *(const unsigned*)(br);
            unsigned b1 = *(const unsigned*)(br + 8);
            asm volatile(
                "mma.sync.aligned.m16n8k16.row.col.f32.f16.f16.f32 "
                "{%0,%1,%2,%3}, {%4,%5,%6,%7}, {%8,%9}, {%0,%1,%2,%3};"
                : "+f"(c[nt][0]), "+f"(c[nt][1]), "+f"(c[nt][2]), "+f"(c[nt][3])
                : "r"(af[s][0]), "r"(af[s][1]), "r"(af[s][2]), "r"(af[s][3]),
                  "r"(b0), "r"(b1));
        }
    }

    // epilogue: bias + fp16 + streaming store
    size_t row0 = (size_t)(e0 + erow + g);
    #pragma unroll
    for (int nt = 0; nt < 16; nt++) {
        float bb0 = s_bias[nt * 8 + tg * 2];
        float bb1 = s_bias[nt * 8 + tg * 2 + 1];
        __half2 h0 = __floats2half2_rn(c[nt][0] + bb0, c[nt][1] + bb1);
        __half2 h1 = __floats2half2_rn(c[nt][2] + bb0, c[nt][3] + bb1);
        __half* base = g_We + row0 * 1024 + n0 + nt * 8 + tg * 2;
        __stcs((unsigned int*)base, *(unsigned int*)&h0);
        __stcs((unsigned int*)(base + 8 * 1024), *(unsigned int*)&h1);
    }
}

// ---------- message + scatter: agg[b,dst] += node[b,src] @ We[e] ----------
// 8 lanes per edge, 4 edges per warp. Streams fp16 We with __ldcs (evict-first).
__global__ void __launch_bounds__(256) msg_kernel(
    const int* __restrict__ esrc, const int* __restrict__ edst)
{
    int gtid = blockIdx.x * 256 + threadIdx.x;
    int warp = gtid >> 5;
    int lane = threadIdx.x & 31;
    int g = lane >> 3, q = lane & 7;
    int e = warp * 4 + g;

    int s = esrc[e], d = edst[e];
    const float4* np = (const float4*)g_hidden + (size_t)s * 8 + q;
    float4 v0 = __ldg(np);
    float4 v1 = __ldg(np + (size_t)N_NODES * 8);

    const __half* wp = g_We + (size_t)e * 1024 + q * 4;
    float4 acc0 = make_float4(0.f, 0.f, 0.f, 0.f);
    float4 acc1 = make_float4(0.f, 0.f, 0.f, 0.f);

    #pragma unroll
    for (int h = 0; h < 32; h++) {
        uint2 wraw = __ldcs((const uint2*)(wp + h * 32));
        float2 w01 = __half22float2(*(__half2*)&wraw.x);
        float2 w23 = __half22float2(*(__half2*)&wraw.y);
        int hq = h >> 2, rc = h & 3;
        float c0 = (rc == 0) ? v0.x : (rc == 1) ? v0.y : (rc == 2) ? v0.z : v0.w;
        float c1 = (rc == 0) ? v1.x : (rc == 1) ? v1.y : (rc == 2) ? v1.z : v1.w;
        float n0 = __shfl_sync(0xffffffffu, c0, hq, 8);
        float n1 = __shfl_sync(0xffffffffu, c1, hq, 8);
        acc0.x = fmaf(n0, w01.x, acc0.x); acc0.y = fmaf(n0, w01.y, acc0.y);
        acc0.z = fmaf(n0, w23.x, acc0.z); acc0.w = fmaf(n0, w23.y, acc0.w);
        acc1.x = fmaf(n1, w01.x, acc1.x); acc1.y = fmaf(n1, w01.y, acc1.y);
        acc1.z = fmaf(n1, w23.x, acc1.z); acc1.w = fmaf(n1, w23.y, acc1.w);
    }
    float* ap0 = g_agg + (size_t)d * 32 + q * 4;
    atomicAdd(ap0 + 0, acc0.x); atomicAdd(ap0 + 1, acc0.y);
    atomicAdd(ap0 + 2, acc0.z); atomicAdd(ap0 + 3, acc0.w);
    float* ap1 = ap0 + (size_t)N_NODES * 32;
    atomicAdd(ap1 + 0, acc1.x); atomicAdd(ap1 + 1, acc1.y);
    atomicAdd(ap1 + 2, acc1.z); atomicAdd(ap1 + 3, acc1.w);
}

// ---------- fused conv_b + ReLU + GRU cell; re-zeroes g_agg for next step ----------
__global__ void __launch_bounds__(128) gru_kernel(
    const float* __restrict__ wih, const float* __restrict__ whh,
    const float* __restrict__ bih, const float* __restrict__ bhh,
    const float* __restrict__ convb,
    float* __restrict__ d_out, int last)
{
    __shared__ float s_wih[3072], s_whh[3072];
    __shared__ float s_bih[96], s_bhh[96], s_cb[32];
    __shared__ float s_h[128][33];

    int t = threadIdx.x;
    for (int i = t; i < 3072; i += 128) { s_wih[i] = wih[i]; s_whh[i] = whh[i]; }
    if (t < 96) { s_bih[t] = bih[t]; s_bhh[t] = bhh[t]; }
    if (t < 32) s_cb[t] = convb[t];
    __syncthreads();

    int idx = blockIdx.x * 128 + t;   // [0, NB)
    ull a2[16], h2[16];
    float4* agp = (float4*)(g_agg + (size_t)idx * 32);
    const float4* hp = (const float4*)(g_hidden + (size_t)idx * 32);
    #pragma unroll
    for (int i = 0; i < 8; i++) {
        float4 av = agp[i];
        av.x = fmaxf(av.x + s_cb[4*i+0], 0.f);
        av.y = fmaxf(av.y + s_cb[4*i+1], 0.f);
        av.z = fmaxf(av.z + s_cb[4*i+2], 0.f);
        av.w = fmaxf(av.w + s_cb[4*i+3], 0.f);
        a2[2*i]   = pack2(av.x, av.y);
        a2[2*i+1] = pack2(av.z, av.w);
        float4 hv = hp[i];
        h2[2*i]   = pack2(hv.x, hv.y);
        h2[2*i+1] = pack2(hv.z, hv.w);
        s_h[t][4*i+0] = hv.x; s_h[t][4*i+1] = hv.y;
        s_h[t][4*i+2] = hv.z; s_h[t][4*i+3] = hv.w;
    }
    // zero agg for next step's atomics
    float4 z = make_float4(0.f, 0.f, 0.f, 0.f);
    #pragma unroll
    for (int i = 0; i < 8; i++) agp[i] = z;

    float* outp = last ? (d_out + (size_t)idx * 32) : (g_hidden + (size_t)idx * 32);

    for (int l = 0; l < 32; l++) {
        ull rx = 0, rh = 0, zx = 0, zh = 0, nx = 0, nh = 0;
        const ull* wr = (const ull*)(s_wih + l * 32);
        const ull* wz = (const ull*)(s_wih + (32 + l) * 32);
        const ull* wn = (const ull*)(s_wih + (64 + l) * 32);
        const ull* ur = (const ull*)(s_whh + l * 32);
        const ull* uz = (const ull*)(s_whh + (32 + l) * 32);
        const ull* un = (const ull*)(s_whh + (64 + l) * 32);
        #pragma unroll
        for (int q = 0; q < 16; q++) {
            fma2(rx, a2[q], wr[q]); fma2(rh, h2[q], ur[q]);
            fma2(zx, a2[q], wz[q]); fma2(zh, h2[q], uz[q]);
            fma2(nx, a2[q], wn[q]); fma2(nh, h2[q], un[q]);
        }
        float2 frx = unpack2(rx), frh = unpack2(rh);
        float rv = sigmoidf_(frx.x + frx.y + frh.x + frh.y + s_bih[l] + s_bhh[l]);
        float2 fzx = unpack2(zx), fzh = unpack2(zh);
        float zv = sigmoidf_(fzx.x + fzx.y + fzh.x + fzh.y + s_bih[32 + l] + s_bhh[32 + l]);
        float2 fnx = unpack2(nx), fnh = unpack2(nh);
        float gxn = fnx.x + fnx.y + s_bih[64 + l];
        float ghn = fnh.x + fnh.y + s_bhh[64 + l];
        float nv = tanhf(fmaf(rv, ghn, gxn));
        float hold = s_h[t][l];
        s_h[t][l] = (1.f - zv) * nv + zv * hold;
    }

    #pragma unroll
    for (int i = 0; i < 8; i++) {
        float4 o;
        o.x = s_h[t][4*i+0]; o.y = s_h[t][4*i+1];
        o.z = s_h[t][4*i+2]; o.w = s_h[t][4*i+3];
        ((float4*)outp)[i] = o;
    }
}

extern "C" void kernel_launch(void* const* d_in, const int* in_sizes, int n_in,
                              void* d_out, int out_size)
{
    const float* x     = (const float*)d_in[0];
    const float* rel   = (const float*)d_in[1];
    const float* pw1   = (const float*)d_in[2];
    const float* pb1   = (const float*)d_in[3];
    const float* pw2   = (const float*)d_in[4];
    const float* pb2   = (const float*)d_in[5];
    const float* ew1   = (const float*)d_in[6];
    const float* eb1   = (const float*)d_in[7];
    const float* ew2   = (const float*)d_in[8];
    const float* eb2   = (const float*)d_in[9];
    const float* convb = (const float*)d_in[10];
    const float* wih   = (const float*)d_in[11];
    const float* whh   = (const float*)d_in[12];
    const float* bih   = (const float*)d_in[13];
    const float* bhh   = (const float*)d_in[14];
    const int*   esrc  = (const int*)d_in[15];
    const int*   edst  = (const int*)d_in[16];
    float* out = (float*)d_out;

    proj_kernel<<<NB / 128, 128>>>(x, pw1, pb1, pw2, pb2);
    bt_prep_kernel<<<32768 / 256, 256>>>(ew2);
    we_gemm_kernel<<<dim3(8, N_EDGES / 128), 256>>>(rel, ew1, eb1, eb2);

    for (int s = 0; s < 3; s++) {
        msg_kernel<<<N_EDGES / 32, 256>>>(esrc, edst);   // 4 edges/warp, 8 warps/block
        gru_kernel<<<NB / 128, 128>>>(wih, whh, bih, bhh, convb, out, s == 2 ? 1 : 0);
    }
}

// round 4
// speedup vs baseline: 1.7292x; 1.1705x over previous
#include <cuda_runtime.h>
#include <cuda_fp16.h>

#define N_NODES 55296
#define N_EDGES 221184
#define NB      110592   // BATCH * N_NODES

typedef unsigned long long ull;

// Scratch (static device arrays: no allocation at launch time)
__device__ __half g_We[(size_t)N_EDGES * 1024];  // [E][h=32][o=32] fp16
__device__ __half g_bt[1024 * 32];               // ew2 transposed: [n][k] fp16
__device__ float g_hidden[(size_t)NB * 32];      // [b][n][32] flattened
__device__ float g_agg[(size_t)NB * 32];

// ---------- packed f32x2 helpers ----------
__device__ __forceinline__ ull pack2(float lo, float hi) {
    ull v; asm("mov.b64 %0, {%1, %2};" : "=l"(v) : "f"(lo), "f"(hi)); return v;
}
__device__ __forceinline__ float2 unpack2(ull v) {
    float2 f; asm("mov.b64 {%0, %1}, %2;" : "=f"(f.x), "=f"(f.y) : "l"(v)); return f;
}
__device__ __forceinline__ void fma2(ull& d, ull a, ull b) {
    asm("fma.rn.f32x2 %0, %1, %2, %0;" : "+l"(d) : "l"(a), "l"(b));
}
__device__ __forceinline__ float sigmoidf_(float x) {
    return __fdividef(1.f, 1.f + __expf(-x));
}
__device__ __forceinline__ void red4(float* p, float a, float b, float c, float d) {
    asm volatile("red.global.add.v4.f32 [%0], {%1,%2,%3,%4};"
                 :: "l"(p), "f"(a), "f"(b), "f"(c), "f"(d) : "memory");
}

// ---------- node projection: h0 = ReLU(x@pw1+pb1)@pw2+pb2 ; also zero g_agg ----------
__global__ void __launch_bounds__(128) proj_kernel(
    const float* __restrict__ x,
    const float* __restrict__ pw1, const float* __restrict__ pb1,
    const float* __restrict__ pw2, const float* __restrict__ pb2)
{
    __shared__ float s_w1[1024], s_w2[1024], s_b1[32], s_b2[32];
    int t = threadIdx.x;
    for (int i = t; i < 1024; i += 128) { s_w1[i] = pw1[i]; s_w2[i] = pw2[i]; }
    if (t < 32) { s_b1[t] = pb1[t]; s_b2[t] = pb2[t]; }
    __syncthreads();

    int idx = blockIdx.x * 128 + t;   // [0, NB)

    // zero agg for the first msg pass
    float4 z = make_float4(0.f, 0.f, 0.f, 0.f);
    float4* zp = (float4*)(g_agg + (size_t)idx * 32);
    #pragma unroll
    for (int j = 0; j < 8; j++) zp[j] = z;

    float v[32];
    const float4* xp = (const float4*)(x + (size_t)idx * 32);
    #pragma unroll
    for (int i = 0; i < 8; i++) {
        float4 xv = xp[i];
        v[4*i+0] = xv.x; v[4*i+1] = xv.y; v[4*i+2] = xv.z; v[4*i+3] = xv.w;
    }
    float4 acc[8];
    #pragma unroll
    for (int j = 0; j < 8; j++) acc[j] = ((const float4*)s_b1)[j];
    #pragma unroll
    for (int c = 0; c < 32; c++) {
        float xv = v[c];
        #pragma unroll
        for (int j = 0; j < 8; j++) {
            float4 w = ((const float4*)s_w1)[c*8 + j];
            acc[j].x = fmaf(xv, w.x, acc[j].x);
            acc[j].y = fmaf(xv, w.y, acc[j].y);
            acc[j].z = fmaf(xv, w.z, acc[j].z);
            acc[j].w = fmaf(xv, w.w, acc[j].w);
        }
    }
    #pragma unroll
    for (int j = 0; j < 8; j++) {
        v[4*j+0] = fmaxf(acc[j].x, 0.f);
        v[4*j+1] = fmaxf(acc[j].y, 0.f);
        v[4*j+2] = fmaxf(acc[j].z, 0.f);
        v[4*j+3] = fmaxf(acc[j].w, 0.f);
    }
    #pragma unroll
    for (int j = 0; j < 8; j++) acc[j] = ((const float4*)s_b2)[j];
    #pragma unroll
    for (int c = 0; c < 32; c++) {
        float xv = v[c];
        #pragma unroll
        for (int j = 0; j < 8; j++) {
            float4 w = ((const float4*)s_w2)[c*8 + j];
            acc[j].x = fmaf(xv, w.x, acc[j].x);
            acc[j].y = fmaf(xv, w.y, acc[j].y);
            acc[j].z = fmaf(xv, w.z, acc[j].z);
            acc[j].w = fmaf(xv, w.w, acc[j].w);
        }
    }
    float4* op = (float4*)(g_hidden + (size_t)idx * 32);
    #pragma unroll
    for (int j = 0; j < 8; j++) op[j] = acc[j];
}

// ---------- prep: g_bt[n][k] = (half)ew2[k][n] ----------
__global__ void bt_prep_kernel(const float* __restrict__ ew2)
{
    int i = blockIdx.x * 256 + threadIdx.x;   // [0, 32768)
    int k = i >> 10, n = i & 1023;
    g_bt[n * 32 + k] = __float2half(ew2[i]);
}

// ---------- edge network GEMM via tensor cores ----------
// C[E,1024] = A[E,32] * B[32,1024], A = ReLU(rel@ew1+eb1), fp16 in, fp32 acc, fp16 out
// Tile: 128 edges x 128 cols, 256 thr (8 warps), each warp: 16 edges x 128 cols.
// Epilogue stages through smem -> STG.128 coalesced stores.
__global__ void __launch_bounds__(256, 2) we_gemm_kernel(
    const float* __restrict__ rel,
    const float* __restrict__ ew1, const float* __restrict__ eb1,
    const float* __restrict__ eb2)
{
    __shared__ __half s_a[128 * 40];    // [e][k], stride 40 (conflict-free frags)
    __shared__ __half s_bt[128 * 40];   // [n][k], stride 40
    __shared__ __align__(16) __half s_stage[8][16][72]; // per-warp [row][64 cols + pad]
    __shared__ float4 s_rel[128];
    __shared__ float  s_w1[128];
    __shared__ float  s_be[32];
    __shared__ float  s_bias[128];

    int t  = threadIdx.x;
    int e0 = blockIdx.y * 128;
    int n0 = blockIdx.x * 128;

    if (t < 128) {
        s_w1[t] = ew1[t];
        s_rel[t] = ((const float4*)rel)[e0 + t];
        s_bias[t] = eb2[n0 + t];
    }
    if (t >= 128 && t < 160) s_be[t - 128] = eb1[t - 128];
    __syncthreads();

    // A prep: ReLU(rel@ew1+eb1) -> half, [e][k]
    #pragma unroll
    for (int i = 0; i < 16; i++) {
        int idx = t + i * 256;
        int k = idx >> 7, e = idx & 127;
        float4 rp = s_rel[e];
        float a = s_be[k];
        a = fmaf(rp.x, s_w1[k],      a);
        a = fmaf(rp.y, s_w1[32 + k], a);
        a = fmaf(rp.z, s_w1[64 + k], a);
        a = fmaf(rp.w, s_w1[96 + k], a);
        s_a[e * 40 + k] = __float2half(fmaxf(a, 0.f));
    }
    // B tile: copy 128 rows of g_bt (32 halves each) into padded smem
    {
        const uint4* src = (const uint4*)(g_bt + (size_t)n0 * 32);
        for (int j = t; j < 512; j += 256) {
            int n = j >> 2, p = j & 3;
            *(uint4*)(s_bt + n * 40 + p * 8) = src[j];
        }
    }
    __syncthreads();

    int w = t >> 5, lane = t & 31;
    int g = lane >> 2, tg = lane & 3;
    int erow = w * 16;

    // A fragments: 2 k-steps of m16k16
    unsigned af[2][4];
    #pragma unroll
    for (int s = 0; s < 2; s++) {
        const __half* ar0 = s_a + (erow + g) * 40 + s * 16 + tg * 2;
        const __half* ar1 = s_a + (erow + g + 8) * 40 + s * 16 + tg * 2;
        af[s][0] = *(const unsigned*)(ar0);
        af[s][1] = *(const unsigned*)(ar1);
        af[s][2] = *(const unsigned*)(ar0 + 8);
        af[s][3] = *(const unsigned*)(ar1 + 8);
    }

    float c[16][4];
    #pragma unroll
    for (int nt = 0; nt < 16; nt++)
        #pragma unroll
        for (int j = 0; j < 4; j++) c[nt][j] = 0.f;

    #pragma unroll
    for (int nt = 0; nt < 16; nt++) {
        #pragma unroll
        for (int s = 0; s < 2; s++) {
            const __half* br = s_bt + (nt * 8 + g) * 40 + s * 16 + tg * 2;
            unsigned b0 = *(const unsigned*)(br);
            unsigned b1 = *(const unsigned*)(br + 8);
            asm volatile(
                "mma.sync.aligned.m16n8k16.row.col.f32.f16.f16.f32 "
                "{%0,%1,%2,%3}, {%4,%5,%6,%7}, {%8,%9}, {%0,%1,%2,%3};"
                : "+f"(c[nt][0]), "+f"(c[nt][1]), "+f"(c[nt][2]), "+f"(c[nt][3])
                : "r"(af[s][0]), "r"(af[s][1]), "r"(af[s][2]), "r"(af[s][3]),
                  "r"(b0), "r"(b1));
        }
    }

    // epilogue: bias + fp16, stage in smem, then coalesced STG.128
    #pragma unroll
    for (int pass = 0; pass < 2; pass++) {
        #pragma unroll
        for (int nt2 = 0; nt2 < 8; nt2++) {
            int nt = pass * 8 + nt2;
            float bb0 = s_bias[nt * 8 + tg * 2];
            float bb1 = s_bias[nt * 8 + tg * 2 + 1];
            __half2 h0 = __floats2half2_rn(c[nt][0] + bb0, c[nt][1] + bb1);
            __half2 h1 = __floats2half2_rn(c[nt][2] + bb0, c[nt][3] + bb1);
            *(__half2*)&s_stage[w][g][nt2 * 8 + tg * 2]     = h0;
            *(__half2*)&s_stage[w][g + 8][nt2 * 8 + tg * 2] = h1;
        }
        __syncwarp();
        #pragma unroll
        for (int i = 0; i < 4; i++) {
            int idx = lane + 32 * i;          // [0,128)
            int r = idx >> 3, c8 = idx & 7;
            uint4 val = *(const uint4*)&s_stage[w][r][c8 * 8];
            __half* dst = g_We + (size_t)(e0 + erow + r) * 1024 + n0 + pass * 64 + c8 * 8;
            __stcs((uint4*)dst, val);
        }
        __syncwarp();
    }
}

// ---------- message + scatter: agg[b,dst] += node[b,src] @ We[e] ----------
// 4 lanes per edge (8 outputs each), 8 edges per warp. LDG.128 streams, red.v4 scatter.
__global__ void __launch_bounds__(256) msg_kernel(
    const int* __restrict__ esrc, const int* __restrict__ edst)
{
    int gtid = blockIdx.x * 256 + threadIdx.x;
    int warp = gtid >> 5;
    int lane = threadIdx.x & 31;
    int sub = lane >> 2, q = lane & 3;
    int e = warp * 8 + sub;

    int s = esrc[e], d = edst[e];

    // this lane's 8 src features per batch (register arrays; full unroll keeps in regs)
    float va[8], vb[8];
    {
        const float4* np = (const float4*)(g_hidden + (size_t)s * 32 + q * 8);
        float4 a0 = __ldg(np), a1 = __ldg(np + 1);
        va[0]=a0.x; va[1]=a0.y; va[2]=a0.z; va[3]=a0.w;
        va[4]=a1.x; va[5]=a1.y; va[6]=a1.z; va[7]=a1.w;
        const float4* np2 = (const float4*)(g_hidden + (size_t)(N_NODES + s) * 32 + q * 8);
        float4 b0 = __ldg(np2), b1 = __ldg(np2 + 1);
        vb[0]=b0.x; vb[1]=b0.y; vb[2]=b0.z; vb[3]=b0.w;
        vb[4]=b1.x; vb[5]=b1.y; vb[6]=b1.z; vb[7]=b1.w;
    }

    const __half* wp = g_We + (size_t)e * 1024 + q * 8;
    float acc0[8], acc1[8];
    #pragma unroll
    for (int i = 0; i < 8; i++) { acc0[i] = 0.f; acc1[i] = 0.f; }

    #pragma unroll
    for (int h = 0; h < 32; h++) {
        uint4 wr = __ldcs((const uint4*)(wp + h * 32));
        float2 w0 = __half22float2(*(__half2*)&wr.x);
        float2 w1 = __half22float2(*(__half2*)&wr.y);
        float2 w2 = __half22float2(*(__half2*)&wr.z);
        float2 w3 = __half22float2(*(__half2*)&wr.w);
        float n0 = __shfl_sync(0xffffffffu, va[h & 7], h >> 3, 4);
        float n1 = __shfl_sync(0xffffffffu, vb[h & 7], h >> 3, 4);
        acc0[0] = fmaf(n0, w0.x, acc0[0]); acc0[1] = fmaf(n0, w0.y, acc0[1]);
        acc0[2] = fmaf(n0, w1.x, acc0[2]); acc0[3] = fmaf(n0, w1.y, acc0[3]);
        acc0[4] = fmaf(n0, w2.x, acc0[4]); acc0[5] = fmaf(n0, w2.y, acc0[5]);
        acc0[6] = fmaf(n0, w3.x, acc0[6]); acc0[7] = fmaf(n0, w3.y, acc0[7]);
        acc1[0] = fmaf(n1, w0.x, acc1[0]); acc1[1] = fmaf(n1, w0.y, acc1[1]);
        acc1[2] = fmaf(n1, w1.x, acc1[2]); acc1[3] = fmaf(n1, w1.y, acc1[3]);
        acc1[4] = fmaf(n1, w2.x, acc1[4]); acc1[5] = fmaf(n1, w2.y, acc1[5]);
        acc1[6] = fmaf(n1, w3.x, acc1[6]); acc1[7] = fmaf(n1, w3.y, acc1[7]);
    }
    float* ap0 = g_agg + (size_t)d * 32 + q * 8;
    red4(ap0,     acc0[0], acc0[1], acc0[2], acc0[3]);
    red4(ap0 + 4, acc0[4], acc0[5], acc0[6], acc0[7]);
    float* ap1 = ap0 + (size_t)N_NODES * 32;
    red4(ap1,     acc1[0], acc1[1], acc1[2], acc1[3]);
    red4(ap1 + 4, acc1[4], acc1[5], acc1[6], acc1[7]);
}

// ---------- fused conv_b + ReLU + GRU cell; re-zeroes g_agg for next step ----------
__global__ void __launch_bounds__(128) gru_kernel(
    const float* __restrict__ wih, const float* __restrict__ whh,
    const float* __restrict__ bih, const float* __restrict__ bhh,
    const float* __restrict__ convb,
    float* __restrict__ d_out, int last)
{
    __shared__ float s_wih[3072], s_whh[3072];
    __shared__ float s_bih[96], s_bhh[96], s_cb[32];
    __shared__ float s_h[128][33];

    int t = threadIdx.x;
    for (int i = t; i < 3072; i += 128) { s_wih[i] = wih[i]; s_whh[i] = whh[i]; }
    if (t < 96) { s_bih[t] = bih[t]; s_bhh[t] = bhh[t]; }
    if (t < 32) s_cb[t] = convb[t];
    __syncthreads();

    int idx = blockIdx.x * 128 + t;   // [0, NB)
    ull a2[16], h2[16];
    float4* agp = (float4*)(g_agg + (size_t)idx * 32);
    const float4* hp = (const float4*)(g_hidden + (size_t)idx * 32);
    #pragma unroll
    for (int i = 0; i < 8; i++) {
        float4 av = agp[i];
        av.x = fmaxf(av.x + s_cb[4*i+0], 0.f);
        av.y = fmaxf(av.y + s_cb[4*i+1], 0.f);
        av.z = fmaxf(av.z + s_cb[4*i+2], 0.f);
        av.w = fmaxf(av.w + s_cb[4*i+3], 0.f);
        a2[2*i]   = pack2(av.x, av.y);
        a2[2*i+1] = pack2(av.z, av.w);
        float4 hv = hp[i];
        h2[2*i]   = pack2(hv.x, hv.y);
        h2[2*i+1] = pack2(hv.z, hv.w);
        s_h[t][4*i+0] = hv.x; s_h[t][4*i+1] = hv.y;
        s_h[t][4*i+2] = hv.z; s_h[t][4*i+3] = hv.w;
    }
    // zero agg for next step's atomics
    float4 z = make_float4(0.f, 0.f, 0.f, 0.f);
    #pragma unroll
    for (int i = 0; i < 8; i++) agp[i] = z;

    float* outp = last ? (d_out + (size_t)idx * 32) : (g_hidden + (size_t)idx * 32);

    for (int l = 0; l < 32; l++) {
        ull rx = 0, rh = 0, zx = 0, zh = 0, nx = 0, nh = 0;
        const ull* wr = (const ull*)(s_wih + l * 32);
        const ull* wz = (const ull*)(s_wih + (32 + l) * 32);
        const ull* wn = (const ull*)(s_wih + (64 + l) * 32);
        const ull* ur = (const ull*)(s_whh + l * 32);
        const ull* uz = (const ull*)(s_whh + (32 + l) * 32);
        const ull* un = (const ull*)(s_whh + (64 + l) * 32);
        #pragma unroll
        for (int q = 0; q < 16; q++) {
            fma2(rx, a2[q], wr[q]); fma2(rh, h2[q], ur[q]);
            fma2(zx, a2[q], wz[q]); fma2(zh, h2[q], uz[q]);
            fma2(nx, a2[q], wn[q]); fma2(nh, h2[q], un[q]);
        }
        float2 frx = unpack2(rx), frh = unpack2(rh);
        float rv = sigmoidf_(frx.x + frx.y + frh.x + frh.y + s_bih[l] + s_bhh[l]);
        float2 fzx = unpack2(zx), fzh = unpack2(zh);
        float zv = sigmoidf_(fzx.x + fzx.y + fzh.x + fzh.y + s_bih[32 + l] + s_bhh[32 + l]);
        float2 fnx = unpack2(nx), fnh = unpack2(nh);
        float gxn = fnx.x + fnx.y + s_bih[64 + l];
        float ghn = fnh.x + fnh.y + s_bhh[64 + l];
        float nv = tanhf(fmaf(rv, ghn, gxn));
        float hold = s_h[t][l];
        s_h[t][l] = (1.f - zv) * nv + zv * hold;
    }

    #pragma unroll
    for (int i = 0; i < 8; i++) {
        float4 o;
        o.x = s_h[t][4*i+0]; o.y = s_h[t][4*i+1];
        o.z = s_h[t][4*i+2]; o.w = s_h[t][4*i+3];
        ((float4*)outp)[i] = o;
    }
}

extern "C" void kernel_launch(void* const* d_in, const int* in_sizes, int n_in,
                              void* d_out, int out_size)
{
    const float* x     = (const float*)d_in[0];
    const float* rel   = (const float*)d_in[1];
    const float* pw1   = (const float*)d_in[2];
    const float* pb1   = (const float*)d_in[3];
    const float* pw2   = (const float*)d_in[4];
    const float* pb2   = (const float*)d_in[5];
    const float* ew1   = (const float*)d_in[6];
    const float* eb1   = (const float*)d_in[7];
    const float* ew2   = (const float*)d_in[8];
    const float* eb2   = (const float*)d_in[9];
    const float* convb = (const float*)d_in[10];
    const float* wih   = (const float*)d_in[11];
    const float* whh   = (const float*)d_in[12];
    const float* bih   = (const float*)d_in[13];
    const float* bhh   = (const float*)d_in[14];
    const int*   esrc  = (const int*)d_in[15];
    const int*   edst  = (const int*)d_in[16];
    float* out = (float*)d_out;

    proj_kernel<<<NB / 128, 128>>>(x, pw1, pb1, pw2, pb2);
    bt_prep_kernel<<<32768 / 256, 256>>>(ew2);
    we_gemm_kernel<<<dim3(8, N_EDGES / 128), 256>>>(rel, ew1, eb1, eb2);

    for (int s = 0; s < 3; s++) {
        msg_kernel<<<N_EDGES / 64, 256>>>(esrc, edst);   // 8 edges/warp, 8 warps/block
        gru_kernel<<<NB / 128, 128>>>(wih, whh, bih, bhh, convb, out, s == 2 ? 1 : 0);
    }
}

// round 7
// speedup vs baseline: 2.2770x; 1.3168x over previous
#include <cuda_runtime.h>
#include <cuda_fp16.h>

#define N_NODES 55296
#define N_EDGES 221184
#define NB      110592   // BATCH * N_NODES

typedef unsigned long long ull;

// Scratch (static device arrays: no allocation at launch time)
__device__ __half g_We[(size_t)N_EDGES * 1024];  // [E][h=32][o=32] fp16
__device__ __half g_bt[1024 * 32];               // ew2 transposed: [n][k] fp16
__device__ float g_hidden[(size_t)NB * 32];      // [b][n][32] flattened
__device__ float g_agg[(size_t)NB * 32];

__device__ __forceinline__ float sigmoidf_(float x) {
    return __fdividef(1.f, 1.f + __expf(-x));
}
__device__ __forceinline__ void red4(float* p, float a, float b, float c, float d) {
    asm volatile("red.global.add.v4.f32 [%0], {%1,%2,%3,%4};"
                 :: "l"(p), "f"(a), "f"(b), "f"(c), "f"(d) : "memory");
}
#define MMA_F32(c0,c1,c2,c3,a0,a1,a2,a3,b0,b1) \
    asm volatile("mma.sync.aligned.m16n8k16.row.col.f32.f16.f16.f32 " \
        "{%0,%1,%2,%3}, {%4,%5,%6,%7}, {%8,%9}, {%0,%1,%2,%3};" \
        : "+f"(c0), "+f"(c1), "+f"(c2), "+f"(c3) \
        : "r"(a0), "r"(a1), "r"(a2), "r"(a3), "r"(b0), "r"(b1))

// ---------- node projection: h0 = ReLU(x@pw1+pb1)@pw2+pb2 ; also zero g_agg ----------
__global__ void __launch_bounds__(128) proj_kernel(
    const float* __restrict__ x,
    const float* __restrict__ pw1, const float* __restrict__ pb1,
    const float* __restrict__ pw2, const float* __restrict__ pb2)
{
    __shared__ float s_w1[1024], s_w2[1024], s_b1[32], s_b2[32];
    int t = threadIdx.x;
    for (int i = t; i < 1024; i += 128) { s_w1[i] = pw1[i]; s_w2[i] = pw2[i]; }
    if (t < 32) { s_b1[t] = pb1[t]; s_b2[t] = pb2[t]; }
    __syncthreads();

    int idx = blockIdx.x * 128 + t;   // [0, NB)

    float4 z = make_float4(0.f, 0.f, 0.f, 0.f);
    float4* zp = (float4*)(g_agg + (size_t)idx * 32);
    #pragma unroll
    for (int j = 0; j < 8; j++) zp[j] = z;

    float v[32];
    const float4* xp = (const float4*)(x + (size_t)idx * 32);
    #pragma unroll
    for (int i = 0; i < 8; i++) {
        float4 xv = xp[i];
        v[4*i+0] = xv.x; v[4*i+1] = xv.y; v[4*i+2] = xv.z; v[4*i+3] = xv.w;
    }
    float4 acc[8];
    #pragma unroll
    for (int j = 0; j < 8; j++) acc[j] = ((const float4*)s_b1)[j];
    #pragma unroll
    for (int c = 0; c < 32; c++) {
        float xv = v[c];
        #pragma unroll
        for (int j = 0; j < 8; j++) {
            float4 w = ((const float4*)s_w1)[c*8 + j];
            acc[j].x = fmaf(xv, w.x, acc[j].x);
            acc[j].y = fmaf(xv, w.y, acc[j].y);
            acc[j].z = fmaf(xv, w.z, acc[j].z);
            acc[j].w = fmaf(xv, w.w, acc[j].w);
        }
    }
    #pragma unroll
    for (int j = 0; j < 8; j++) {
        v[4*j+0] = fmaxf(acc[j].x, 0.f);
        v[4*j+1] = fmaxf(acc[j].y, 0.f);
        v[4*j+2] = fmaxf(acc[j].z, 0.f);
        v[4*j+3] = fmaxf(acc[j].w, 0.f);
    }
    #pragma unroll
    for (int j = 0; j < 8; j++) acc[j] = ((const float4*)s_b2)[j];
    #pragma unroll
    for (int c = 0; c < 32; c++) {
        float xv = v[c];
        #pragma unroll
        for (int j = 0; j < 8; j++) {
            float4 w = ((const float4*)s_w2)[c*8 + j];
            acc[j].x = fmaf(xv, w.x, acc[j].x);
            acc[j].y = fmaf(xv, w.y, acc[j].y);
            acc[j].z = fmaf(xv, w.z, acc[j].z);
            acc[j].w = fmaf(xv, w.w, acc[j].w);
        }
    }
    float4* op = (float4*)(g_hidden + (size_t)idx * 32);
    #pragma unroll
    for (int j = 0; j < 8; j++) op[j] = acc[j];
}

// ---------- prep: g_bt[n][k] = (half)ew2[k][n] ----------
__global__ void bt_prep_kernel(const float* __restrict__ ew2)
{
    int i = blockIdx.x * 256 + threadIdx.x;   // [0, 32768)
    int k = i >> 10, n = i & 1023;
    g_bt[n * 32 + k] = __float2half(ew2[i]);
}

// ---------- edge network GEMM via tensor cores (f16 accumulate) ----------
__global__ void __launch_bounds__(256, 2) we_gemm_kernel(
    const float* __restrict__ rel,
    const float* __restrict__ ew1, const float* __restrict__ eb1,
    const float* __restrict__ eb2)
{
    __shared__ __half s_a[128 * 40];    // [e][k]
    __shared__ __half s_bt[128 * 40];   // [n][k]
    __shared__ __align__(16) __half s_stage[8][16][72];
    __shared__ float4 s_rel[128];
    __shared__ float  s_w1[128];
    __shared__ float  s_be[32];
    __shared__ float  s_bias[128];

    int t  = threadIdx.x;
    int e0 = blockIdx.y * 128;
    int n0 = blockIdx.x * 128;

    if (t < 128) {
        s_w1[t] = ew1[t];
        s_rel[t] = ((const float4*)rel)[e0 + t];
        s_bias[t] = eb2[n0 + t];
    }
    if (t >= 128 && t < 160) s_be[t - 128] = eb1[t - 128];
    __syncthreads();

    #pragma unroll
    for (int i = 0; i < 16; i++) {
        int idx = t + i * 256;
        int k = idx >> 7, e = idx & 127;
        float4 rp = s_rel[e];
        float a = s_be[k];
        a = fmaf(rp.x, s_w1[k],      a);
        a = fmaf(rp.y, s_w1[32 + k], a);
        a = fmaf(rp.z, s_w1[64 + k], a);
        a = fmaf(rp.w, s_w1[96 + k], a);
        s_a[e * 40 + k] = __float2half(fmaxf(a, 0.f));
    }
    {
        const uint4* src = (const uint4*)(g_bt + (size_t)n0 * 32);
        for (int j = t; j < 512; j += 256) {
            int n = j >> 2, p = j & 3;
            *(uint4*)(s_bt + n * 40 + p * 8) = src[j];
        }
    }
    __syncthreads();

    int w = t >> 5, lane = t & 31;
    int g = lane >> 2, tg = lane & 3;
    int erow = w * 16;

    unsigned af[2][4];
    #pragma unroll
    for (int s = 0; s < 2; s++) {
        const __half* ar0 = s_a + (erow + g) * 40 + s * 16 + tg * 2;
        const __half* ar1 = s_a + (erow + g + 8) * 40 + s * 16 + tg * 2;
        af[s][0] = *(const unsigned*)(ar0);
        af[s][1] = *(const unsigned*)(ar1);
        af[s][2] = *(const unsigned*)(ar0 + 8);
        af[s][3] = *(const unsigned*)(ar1 + 8);
    }

    unsigned hc[16][2];
    #pragma unroll
    for (int nt = 0; nt < 16; nt++) { hc[nt][0] = 0u; hc[nt][1] = 0u; }

    #pragma unroll
    for (int nt = 0; nt < 16; nt++) {
        #pragma unroll
        for (int s = 0; s < 2; s++) {
            const __half* br = s_bt + (nt * 8 + g) * 40 + s * 16 + tg * 2;
            unsigned b0 = *(const unsigned*)(br);
            unsigned b1 = *(const unsigned*)(br + 8);
            asm volatile(
                "mma.sync.aligned.m16n8k16.row.col.f16.f16.f16.f16 "
                "{%0,%1}, {%2,%3,%4,%5}, {%6,%7}, {%0,%1};"
                : "+r"(hc[nt][0]), "+r"(hc[nt][1])
                : "r"(af[s][0]), "r"(af[s][1]), "r"(af[s][2]), "r"(af[s][3]),
                  "r"(b0), "r"(b1));
        }
    }

    // epilogue: bias (half2) + stage + coalesced STG.128
    #pragma unroll
    for (int pass = 0; pass < 2; pass++) {
        #pragma unroll
        for (int nt2 = 0; nt2 < 8; nt2++) {
            int nt = pass * 8 + nt2;
            __half2 bb = __floats2half2_rn(s_bias[nt * 8 + tg * 2], s_bias[nt * 8 + tg * 2 + 1]);
            __half2 v0 = __hadd2(*(__half2*)&hc[nt][0], bb);
            __half2 v1 = __hadd2(*(__half2*)&hc[nt][1], bb);
            *(__half2*)&s_stage[w][g][nt2 * 8 + tg * 2]     = v0;
            *(__half2*)&s_stage[w][g + 8][nt2 * 8 + tg * 2] = v1;
        }
        __syncwarp();
        #pragma unroll
        for (int i = 0; i < 4; i++) {
            int idx = lane + 32 * i;
            int r = idx >> 3, c8 = idx & 7;
            uint4 val = *(const uint4*)&s_stage[w][r][c8 * 8];
            __half* dst = g_We + (size_t)(e0 + erow + r) * 1024 + n0 + pass * 64 + c8 * 8;
            __stcs((uint4*)dst, val);
        }
        __syncwarp();
    }
}

// ---------- message + scatter ----------
__global__ void __launch_bounds__(256) msg_kernel(
    const int* __restrict__ esrc, const int* __restrict__ edst)
{
    int gtid = blockIdx.x * 256 + threadIdx.x;
    int warp = gtid >> 5;
    int lane = threadIdx.x & 31;
    int sub = lane >> 2, q = lane & 3;
    int e = warp * 8 + sub;

    int s = esrc[e], d = edst[e];

    float va[8], vb[8];
    {
        const float4* np = (const float4*)(g_hidden + (size_t)s * 32 + q * 8);
        float4 a0 = __ldg(np), a1 = __ldg(np + 1);
        va[0]=a0.x; va[1]=a0.y; va[2]=a0.z; va[3]=a0.w;
        va[4]=a1.x; va[5]=a1.y; va[6]=a1.z; va[7]=a1.w;
        const float4* np2 = (const float4*)(g_hidden + (size_t)(N_NODES + s) * 32 + q * 8);
        float4 b0 = __ldg(np2), b1 = __ldg(np2 + 1);
        vb[0]=b0.x; vb[1]=b0.y; vb[2]=b0.z; vb[3]=b0.w;
        vb[4]=b1.x; vb[5]=b1.y; vb[6]=b1.z; vb[7]=b1.w;
    }

    const __half* wp = g_We + (size_t)e * 1024 + q * 8;
    float acc0[8], acc1[8];
    #pragma unroll
    for (int i = 0; i < 8; i++) { acc0[i] = 0.f; acc1[i] = 0.f; }

    #pragma unroll
    for (int h = 0; h < 32; h++) {
        uint4 wr = __ldcs((const uint4*)(wp + h * 32));
        float2 w0 = __half22float2(*(__half2*)&wr.x);
        float2 w1 = __half22float2(*(__half2*)&wr.y);
        float2 w2 = __half22float2(*(__half2*)&wr.z);
        float2 w3 = __half22float2(*(__half2*)&wr.w);
        float n0 = __shfl_sync(0xffffffffu, va[h & 7], h >> 3, 4);
        float n1 = __shfl_sync(0xffffffffu, vb[h & 7], h >> 3, 4);
        acc0[0] = fmaf(n0, w0.x, acc0[0]); acc0[1] = fmaf(n0, w0.y, acc0[1]);
        acc0[2] = fmaf(n0, w1.x, acc0[2]); acc0[3] = fmaf(n0, w1.y, acc0[3]);
        acc0[4] = fmaf(n0, w2.x, acc0[4]); acc0[5] = fmaf(n0, w2.y, acc0[5]);
        acc0[6] = fmaf(n0, w3.x, acc0[6]); acc0[7] = fmaf(n0, w3.y, acc0[7]);
        acc1[0] = fmaf(n1, w0.x, acc1[0]); acc1[1] = fmaf(n1, w0.y, acc1[1]);
        acc1[2] = fmaf(n1, w1.x, acc1[2]); acc1[3] = fmaf(n1, w1.y, acc1[3]);
        acc1[4] = fmaf(n1, w2.x, acc1[4]); acc1[5] = fmaf(n1, w2.y, acc1[5]);
        acc1[6] = fmaf(n1, w3.x, acc1[6]); acc1[7] = fmaf(n1, w3.y, acc1[7]);
    }
    float* ap0 = g_agg + (size_t)d * 32 + q * 8;
    red4(ap0,     acc0[0], acc0[1], acc0[2], acc0[3]);
    red4(ap0 + 4, acc0[4], acc0[5], acc0[6], acc0[7]);
    float* ap1 = ap0 + (size_t)N_NODES * 32;
    red4(ap1,     acc1[0], acc1[1], acc1[2], acc1[3]);
    red4(ap1 + 4, acc1[4], acc1[5], acc1[6], acc1[7]);
}

// ---------- GRU via tensor cores: gx = x@Wih^T, gh = h@Whh^T (m16n8k16) ----------
// 256 thr = 8 warps, each warp 16 rows. Gate math fp32 in fragment layout.
__global__ void __launch_bounds__(256) gru_kernel(
    const float* __restrict__ wih, const float* __restrict__ whh,
    const float* __restrict__ bih, const float* __restrict__ bhh,
    const float* __restrict__ convb,
    float* __restrict__ d_out, int last)
{
    __shared__ __half s_wi[96 * 40];
    __shared__ __half s_wh[96 * 40];
    __shared__ float s_bi[96], s_bh[96], s_cb[32];
    __shared__ __align__(16) char s_buf[8][2880];

    int t = threadIdx.x;
    for (int i = t; i < 3072; i += 256) {
        int n = i >> 5, k = i & 31;
        s_wi[n * 40 + k] = __float2half(wih[i]);
        s_wh[n * 40 + k] = __float2half(whh[i]);
    }
    if (t < 96) { s_bi[t] = bih[t]; s_bh[t] = bhh[t]; }
    if (t >= 128 && t < 160) s_cb[t - 128] = convb[t - 128];
    __syncthreads();

    int w = t >> 5, lane = t & 31;
    int wb = blockIdx.x * 128 + w * 16;         // first row of this warp
    __half* sx = (__half*)s_buf[w];              // [16][40] fp16 x tile
    __half* sh = (__half*)(s_buf[w] + 1280);     // [16][40] fp16 hidden tile
    float*  so = (float*)s_buf[w];               // [16][36] fp32 out (reused)

    int r0 = lane >> 3, c4 = (lane & 7) * 4;
    float4 cb = *(float4*)&s_cb[c4];
    #pragma unroll
    for (int i = 0; i < 4; i++) {
        int row = r0 + i * 4;
        float4 av = *(const float4*)(g_agg + (size_t)(wb + row) * 32 + c4);
        *(__half2*)(sx + row * 40 + c4)     = __floats2half2_rn(fmaxf(av.x + cb.x, 0.f), fmaxf(av.y + cb.y, 0.f));
        *(__half2*)(sx + row * 40 + c4 + 2) = __floats2half2_rn(fmaxf(av.z + cb.z, 0.f), fmaxf(av.w + cb.w, 0.f));
        float4 hv = *(const float4*)(g_hidden + (size_t)(wb + row) * 32 + c4);
        *(__half2*)(sh + row * 40 + c4)     = __floats2half2_rn(hv.x, hv.y);
        *(__half2*)(sh + row * 40 + c4 + 2) = __floats2half2_rn(hv.z, hv.w);
    }
    __syncwarp();

    int g = lane >> 2, tg = lane & 3;
    unsigned af[2][4], hf[2][4];
    #pragma unroll
    for (int s = 0; s < 2; s++) {
        const __half* xr0 = sx + g * 40 + s * 16 + tg * 2;
        const __half* xr1 = sx + (g + 8) * 40 + s * 16 + tg * 2;
        af[s][0] = *(const unsigned*)(xr0);
        af[s][1] = *(const unsigned*)(xr1);
        af[s][2] = *(const unsigned*)(xr0 + 8);
        af[s][3] = *(const unsigned*)(xr1 + 8);
        const __half* hr0 = sh + g * 40 + s * 16 + tg * 2;
        const __half* hr1 = sh + (g + 8) * 40 + s * 16 + tg * 2;
        hf[s][0] = *(const unsigned*)(hr0);
        hf[s][1] = *(const unsigned*)(hr1);
        hf[s][2] = *(const unsigned*)(hr0 + 8);
        hf[s][3] = *(const unsigned*)(hr1 + 8);
    }
    __syncwarp();   // frags in regs; s_buf reusable for output staging

    float* outp = last ? d_out : g_hidden;

    #pragma unroll
    for (int cg = 0; cg < 4; cg++) {
        float xr[4] = {0,0,0,0}, xz[4] = {0,0,0,0}, xn[4] = {0,0,0,0};
        float hr[4] = {0,0,0,0}, hz[4] = {0,0,0,0}, hn[4] = {0,0,0,0};
        #pragma unroll
        for (int s = 0; s < 2; s++) {
            const __half* p;
            unsigned b0, b1;
            p = s_wi + (cg * 8 + g) * 40 + s * 16 + tg * 2;
            b0 = *(const unsigned*)p; b1 = *(const unsigned*)(p + 8);
            MMA_F32(xr[0], xr[1], xr[2], xr[3], af[s][0], af[s][1], af[s][2], af[s][3], b0, b1);
            p = s_wi + (32 + cg * 8 + g) * 40 + s * 16 + tg * 2;
            b0 = *(const unsigned*)p; b1 = *(const unsigned*)(p + 8);
            MMA_F32(xz[0], xz[1], xz[2], xz[3], af[s][0], af[s][1], af[s][2], af[s][3], b0, b1);
            p = s_wi + (64 + cg * 8 + g) * 40 + s * 16 + tg * 2;
            b0 = *(const unsigned*)p; b1 = *(const unsigned*)(p + 8);
            MMA_F32(xn[0], xn[1], xn[2], xn[3], af[s][0], af[s][1], af[s][2], af[s][3], b0, b1);
            p = s_wh + (cg * 8 + g) * 40 + s * 16 + tg * 2;
            b0 = *(const unsigned*)p; b1 = *(const unsigned*)(p + 8);
            MMA_F32(hr[0], hr[1], hr[2], hr[3], hf[s][0], hf[s][1], hf[s][2], hf[s][3], b0, b1);
            p = s_wh + (32 + cg * 8 + g) * 40 + s * 16 + tg * 2;
            b0 = *(const unsigned*)p; b1 = *(const unsigned*)(p + 8);
            MMA_F32(hz[0], hz[1], hz[2], hz[3], hf[s][0], hf[s][1], hf[s][2], hf[s][3], b0, b1);
            p = s_wh + (64 + cg * 8 + g) * 40 + s * 16 + tg * 2;
            b0 = *(const unsigned*)p; b1 = *(const unsigned*)(p + 8);
            MMA_F32(hn[0], hn[1], hn[2], hn[3], hf[s][0], hf[s][1], hf[s][2], hf[s][3], b0, b1);
        }
        int u0 = cg * 8 + tg * 2;
        float2 bir = *(float2*)&s_bi[u0],      bhr = *(float2*)&s_bh[u0];
        float2 biz = *(float2*)&s_bi[32 + u0], bhz = *(float2*)&s_bh[32 + u0];
        float2 bin = *(float2*)&s_bi[64 + u0], bhn = *(float2*)&s_bh[64 + u0];
        #pragma unroll
        for (int jp = 0; jp < 2; jp++) {          // jp=0: row g (j 0,1); jp=1: row g+8 (j 2,3)
            int rl = g + jp * 8;
            float2 hold = *(const float2*)(g_hidden + (size_t)(wb + rl) * 32 + u0);
            #pragma unroll
            for (int jj = 0; jj < 2; jj++) {
                int j = jp * 2 + jj;
                float bi_r = jj ? bir.y : bir.x, bh_r = jj ? bhr.y : bhr.x;
                float bi_z = jj ? biz.y : biz.x, bh_z = jj ? bhz.y : bhz.x;
                float bi_n = jj ? bin.y : bin.x, bh_n = jj ? bhn.y : bhn.x;
                float ho = jj ? hold.y : hold.x;
                float rv = sigmoidf_(xr[j] + hr[j] + bi_r + bh_r);
                float zv = sigmoidf_(xz[j] + hz[j] + bi_z + bh_z);
                float nv = tanhf(xn[j] + bi_n + rv * (hn[j] + bh_n));
                so[rl * 36 + u0 + jj] = (1.f - zv) * nv + zv * ho;
            }
        }
    }
    __syncwarp();

    float4 z4 = make_float4(0.f, 0.f, 0.f, 0.f);
    #pragma unroll
    for (int i = 0; i < 4; i++) {
        int row = r0 + i * 4;
        float4 val = *(float4*)(so + row * 36 + c4);
        *(float4*)(outp + (size_t)(wb + row) * 32 + c4) = val;
        *(float4*)(g_agg + (size_t)(wb + row) * 32 + c4) = z4;
    }
}

extern "C" void kernel_launch(void* const* d_in, const int* in_sizes, int n_in,
                              void* d_out, int out_size)
{
    const float* x     = (const float*)d_in[0];
    const float* rel   = (const float*)d_in[1];
    const float* pw1   = (const float*)d_in[2];
    const float* pb1   = (const float*)d_in[3];
    const float* pw2   = (const float*)d_in[4];
    const float* pb2   = (const float*)d_in[5];
    const float* ew1   = (const float*)d_in[6];
    const float* eb1   = (const float*)d_in[7];
    const float* ew2   = (const float*)d_in[8];
    const float* eb2   = (const float*)d_in[9];
    const float* convb = (const float*)d_in[10];
    const float* wih   = (const float*)d_in[11];
    const float* whh   = (const float*)d_in[12];
    const float* bih   = (const float*)d_in[13];
    const float* bhh   = (const float*)d_in[14];
    const int*   esrc  = (const int*)d_in[15];
    const int*   edst  = (const int*)d_in[16];
    float* out = (float*)d_out;

    proj_kernel<<<NB / 128, 128>>>(x, pw1, pb1, pw2, pb2);
    bt_prep_kernel<<<32768 / 256, 256>>>(ew2);
    we_gemm_kernel<<<dim3(8, N_EDGES / 128), 256>>>(rel, ew1, eb1, eb2);

    for (int s = 0; s < 3; s++) {
        msg_kernel<<<N_EDGES / 64, 256>>>(esrc, edst);
        gru_kernel<<<NB / 128, 256>>>(wih, whh, bih, bhh, convb, out, s == 2 ? 1 : 0);
    }
}

// round 8
// speedup vs baseline: 2.2933x; 1.0071x over previous
#include <cuda_runtime.h>
#include <cuda_fp16.h>

#define N_NODES 55296
#define N_EDGES 221184
#define NB      110592   // BATCH * N_NODES

typedef unsigned long long ull;

// Scratch (static device arrays: no allocation at launch time)
__device__ __half g_We[(size_t)N_EDGES * 1024];  // [E][h=32][o=32] fp16
__device__ __half g_bt[1024 * 32];               // ew2 transposed: [n][k] fp16
__device__ float g_hidden[(size_t)NB * 32];      // [b][n][32] flattened
__device__ float g_agg[(size_t)NB * 32];

__device__ __forceinline__ float sigmoidf_(float x) {
    return __fdividef(1.f, 1.f + __expf(-x));
}
__device__ __forceinline__ void red4(float* p, float a, float b, float c, float d) {
    asm volatile("red.global.add.v4.f32 [%0], {%1,%2,%3,%4};"
                 :: "l"(p), "f"(a), "f"(b), "f"(c), "f"(d) : "memory");
}
#define MMA_F32(c0,c1,c2,c3,a0,a1,a2,a3,b0,b1) \
    asm volatile("mma.sync.aligned.m16n8k16.row.col.f32.f16.f16.f32 " \
        "{%0,%1,%2,%3}, {%4,%5,%6,%7}, {%8,%9}, {%0,%1,%2,%3};" \
        : "+f"(c0), "+f"(c1), "+f"(c2), "+f"(c3) \
        : "r"(a0), "r"(a1), "r"(a2), "r"(a3), "r"(b0), "r"(b1))

// ---------- node projection: h0 = ReLU(x@pw1+pb1)@pw2+pb2 ; also zero g_agg ----------
__global__ void __launch_bounds__(128) proj_kernel(
    const float* __restrict__ x,
    const float* __restrict__ pw1, const float* __restrict__ pb1,
    const float* __restrict__ pw2, const float* __restrict__ pb2)
{
    __shared__ float s_w1[1024], s_w2[1024], s_b1[32], s_b2[32];
    int t = threadIdx.x;
    for (int i = t; i < 1024; i += 128) { s_w1[i] = pw1[i]; s_w2[i] = pw2[i]; }
    if (t < 32) { s_b1[t] = pb1[t]; s_b2[t] = pb2[t]; }
    __syncthreads();

    int idx = blockIdx.x * 128 + t;   // [0, NB)

    float4 z = make_float4(0.f, 0.f, 0.f, 0.f);
    float4* zp = (float4*)(g_agg + (size_t)idx * 32);
    #pragma unroll
    for (int j = 0; j < 8; j++) zp[j] = z;

    float v[32];
    const float4* xp = (const float4*)(x + (size_t)idx * 32);
    #pragma unroll
    for (int i = 0; i < 8; i++) {
        float4 xv = xp[i];
        v[4*i+0] = xv.x; v[4*i+1] = xv.y; v[4*i+2] = xv.z; v[4*i+3] = xv.w;
    }
    float4 acc[8];
    #pragma unroll
    for (int j = 0; j < 8; j++) acc[j] = ((const float4*)s_b1)[j];
    #pragma unroll
    for (int c = 0; c < 32; c++) {
        float xv = v[c];
        #pragma unroll
        for (int j = 0; j < 8; j++) {
            float4 w = ((const float4*)s_w1)[c*8 + j];
            acc[j].x = fmaf(xv, w.x, acc[j].x);
            acc[j].y = fmaf(xv, w.y, acc[j].y);
            acc[j].z = fmaf(xv, w.z, acc[j].z);
            acc[j].w = fmaf(xv, w.w, acc[j].w);
        }
    }
    #pragma unroll
    for (int j = 0; j < 8; j++) {
        v[4*j+0] = fmaxf(acc[j].x, 0.f);
        v[4*j+1] = fmaxf(acc[j].y, 0.f);
        v[4*j+2] = fmaxf(acc[j].z, 0.f);
        v[4*j+3] = fmaxf(acc[j].w, 0.f);
    }
    #pragma unroll
    for (int j = 0; j < 8; j++) acc[j] = ((const float4*)s_b2)[j];
    #pragma unroll
    for (int c = 0; c < 32; c++) {
        float xv = v[c];
        #pragma unroll
        for (int j = 0; j < 8; j++) {
            float4 w = ((const float4*)s_w2)[c*8 + j];
            acc[j].x = fmaf(xv, w.x, acc[j].x);
            acc[j].y = fmaf(xv, w.y, acc[j].y);
            acc[j].z = fmaf(xv, w.z, acc[j].z);
            acc[j].w = fmaf(xv, w.w, acc[j].w);
        }
    }
    float4* op = (float4*)(g_hidden + (size_t)idx * 32);
    #pragma unroll
    for (int j = 0; j < 8; j++) op[j] = acc[j];
}

// ---------- prep: g_bt[n][k] = (half)ew2[k][n] ----------
__global__ void bt_prep_kernel(const float* __restrict__ ew2)
{
    int i = blockIdx.x * 256 + threadIdx.x;   // [0, 32768)
    int k = i >> 10, n = i & 1023;
    g_bt[n * 32 + k] = __float2half(ew2[i]);
}

// ---------- edge network GEMM via tensor cores (f16 accumulate) ----------
__global__ void __launch_bounds__(256, 2) we_gemm_kernel(
    const float* __restrict__ rel,
    const float* __restrict__ ew1, const float* __restrict__ eb1,
    const float* __restrict__ eb2)
{
    __shared__ __half s_a[128 * 40];    // [e][k]
    __shared__ __half s_bt[128 * 40];   // [n][k]
    __shared__ __align__(16) __half s_stage[8][16][72];
    __shared__ float4 s_rel[128];
    __shared__ float  s_w1[128];
    __shared__ float  s_be[32];
    __shared__ float  s_bias[128];

    int t  = threadIdx.x;
    int e0 = blockIdx.y * 128;
    int n0 = blockIdx.x * 128;

    if (t < 128) {
        s_w1[t] = ew1[t];
        s_rel[t] = ((const float4*)rel)[e0 + t];
        s_bias[t] = eb2[n0 + t];
    }
    if (t >= 128 && t < 160) s_be[t - 128] = eb1[t - 128];
    __syncthreads();

    #pragma unroll
    for (int i = 0; i < 16; i++) {
        int idx = t + i * 256;
        int k = idx >> 7, e = idx & 127;
        float4 rp = s_rel[e];
        float a = s_be[k];
        a = fmaf(rp.x, s_w1[k],      a);
        a = fmaf(rp.y, s_w1[32 + k], a);
        a = fmaf(rp.z, s_w1[64 + k], a);
        a = fmaf(rp.w, s_w1[96 + k], a);
        s_a[e * 40 + k] = __float2half(fmaxf(a, 0.f));
    }
    {
        const uint4* src = (const uint4*)(g_bt + (size_t)n0 * 32);
        for (int j = t; j < 512; j += 256) {
            int n = j >> 2, p = j & 3;
            *(uint4*)(s_bt + n * 40 + p * 8) = src[j];
        }
    }
    __syncthreads();

    int w = t >> 5, lane = t & 31;
    int g = lane >> 2, tg = lane & 3;
    int erow = w * 16;

    unsigned af[2][4];
    #pragma unroll
    for (int s = 0; s < 2; s++) {
        const __half* ar0 = s_a + (erow + g) * 40 + s * 16 + tg * 2;
        const __half* ar1 = s_a + (erow + g + 8) * 40 + s * 16 + tg * 2;
        af[s][0] = *(const unsigned*)(ar0);
        af[s][1] = *(const unsigned*)(ar1);
        af[s][2] = *(const unsigned*)(ar0 + 8);
        af[s][3] = *(const unsigned*)(ar1 + 8);
    }

    unsigned hc[16][2];
    #pragma unroll
    for (int nt = 0; nt < 16; nt++) { hc[nt][0] = 0u; hc[nt][1] = 0u; }

    #pragma unroll
    for (int nt = 0; nt < 16; nt++) {
        #pragma unroll
        for (int s = 0; s < 2; s++) {
            const __half* br = s_bt + (nt * 8 + g) * 40 + s * 16 + tg * 2;
            unsigned b0 = *(const unsigned*)(br);
            unsigned b1 = *(const unsigned*)(br + 8);
            asm volatile(
                "mma.sync.aligned.m16n8k16.row.col.f16.f16.f16.f16 "
                "{%0,%1}, {%2,%3,%4,%5}, {%6,%7}, {%0,%1};"
                : "+r"(hc[nt][0]), "+r"(hc[nt][1])
                : "r"(af[s][0]), "r"(af[s][1]), "r"(af[s][2]), "r"(af[s][3]),
                  "r"(b0), "r"(b1));
        }
    }

    // epilogue: bias (half2) + stage + coalesced STG.128
    #pragma unroll
    for (int pass = 0; pass < 2; pass++) {
        #pragma unroll
        for (int nt2 = 0; nt2 < 8; nt2++) {
            int nt = pass * 8 + nt2;
            __half2 bb = __floats2half2_rn(s_bias[nt * 8 + tg * 2], s_bias[nt * 8 + tg * 2 + 1]);
            __half2 v0 = __hadd2(*(__half2*)&hc[nt][0], bb);
            __half2 v1 = __hadd2(*(__half2*)&hc[nt][1], bb);
            *(__half2*)&s_stage[w][g][nt2 * 8 + tg * 2]     = v0;
            *(__half2*)&s_stage[w][g + 8][nt2 * 8 + tg * 2] = v1;
        }
        __syncwarp();
        #pragma unroll
        for (int i = 0; i < 4; i++) {
            int idx = lane + 32 * i;
            int r = idx >> 3, c8 = idx & 7;
            uint4 val = *(const uint4*)&s_stage[w][r][c8 * 8];
            __half* dst = g_We + (size_t)(e0 + erow + r) * 1024 + n0 + pass * 64 + c8 * 8;
            __stcs((uint4*)dst, val);
        }
        __syncwarp();
    }
}

// ---------- message + scatter ----------
__global__ void __launch_bounds__(256) msg_kernel(
    const int* __restrict__ esrc, const int* __restrict__ edst)
{
    int gtid = blockIdx.x * 256 + threadIdx.x;
    int warp = gtid >> 5;
    int lane = threadIdx.x & 31;
    int sub = lane >> 2, q = lane & 3;
    int e = warp * 8 + sub;

    int s = esrc[e], d = edst[e];

    float va[8], vb[8];
    {
        const float4* np = (const float4*)(g_hidden + (size_t)s * 32 + q * 8);
        float4 a0 = __ldg(np), a1 = __ldg(np + 1);
        va[0]=a0.x; va[1]=a0.y; va[2]=a0.z; va[3]=a0.w;
        va[4]=a1.x; va[5]=a1.y; va[6]=a1.z; va[7]=a1.w;
        const float4* np2 = (const float4*)(g_hidden + (size_t)(N_NODES + s) * 32 + q * 8);
        float4 b0 = __ldg(np2), b1 = __ldg(np2 + 1);
        vb[0]=b0.x; vb[1]=b0.y; vb[2]=b0.z; vb[3]=b0.w;
        vb[4]=b1.x; vb[5]=b1.y; vb[6]=b1.z; vb[7]=b1.w;
    }

    const __half* wp = g_We + (size_t)e * 1024 + q * 8;
    float acc0[8], acc1[8];
    #pragma unroll
    for (int i = 0; i < 8; i++) { acc0[i] = 0.f; acc1[i] = 0.f; }

    #pragma unroll
    for (int h = 0; h < 32; h++) {
        uint4 wr = __ldcs((const uint4*)(wp + h * 32));
        float2 w0 = __half22float2(*(__half2*)&wr.x);
        float2 w1 = __half22float2(*(__half2*)&wr.y);
        float2 w2 = __half22float2(*(__half2*)&wr.z);
        float2 w3 = __half22float2(*(__half2*)&wr.w);
        float n0 = __shfl_sync(0xffffffffu, va[h & 7], h >> 3, 4);
        float n1 = __shfl_sync(0xffffffffu, vb[h & 7], h >> 3, 4);
        acc0[0] = fmaf(n0, w0.x, acc0[0]); acc0[1] = fmaf(n0, w0.y, acc0[1]);
        acc0[2] = fmaf(n0, w1.x, acc0[2]); acc0[3] = fmaf(n0, w1.y, acc0[3]);
        acc0[4] = fmaf(n0, w2.x, acc0[4]); acc0[5] = fmaf(n0, w2.y, acc0[5]);
        acc0[6] = fmaf(n0, w3.x, acc0[6]); acc0[7] = fmaf(n0, w3.y, acc0[7]);
        acc1[0] = fmaf(n1, w0.x, acc1[0]); acc1[1] = fmaf(n1, w0.y, acc1[1]);
        acc1[2] = fmaf(n1, w1.x, acc1[2]); acc1[3] = fmaf(n1, w1.y, acc1[3]);
        acc1[4] = fmaf(n1, w2.x, acc1[4]); acc1[5] = fmaf(n1, w2.y, acc1[5]);
        acc1[6] = fmaf(n1, w3.x, acc1[6]); acc1[7] = fmaf(n1, w3.y, acc1[7]);
    }
    float* ap0 = g_agg + (size_t)d * 32 + q * 8;
    red4(ap0,     acc0[0], acc0[1], acc0[2], acc0[3]);
    red4(ap0 + 4, acc0[4], acc0[5], acc0[6], acc0[7]);
    float* ap1 = ap0 + (size_t)N_NODES * 32;
    red4(ap1,     acc1[0], acc1[1], acc1[2], acc1[3]);
    red4(ap1 + 4, acc1[4], acc1[5], acc1[6], acc1[7]);
}

// ---------- GRU via tensor cores: gx = x@Wih^T, gh = h@Whh^T (m16n8k16) ----------
// 256 thr = 8 warps, each warp 16 rows. Gate math fp32 in fragment layout.
__global__ void __launch_bounds__(256) gru_kernel(
    const float* __restrict__ wih, const float* __restrict__ whh,
    const float* __restrict__ bih, const float* __restrict__ bhh,
    const float* __restrict__ convb,
    float* __restrict__ d_out, int last)
{
    __shared__ __half s_wi[96 * 40];
    __shared__ __half s_wh[96 * 40];
    __shared__ float s_bi[96], s_bh[96], s_cb[32];
    __shared__ __align__(16) char s_buf[8][2880];

    int t = threadIdx.x;
    for (int i = t; i < 3072; i += 256) {
        int n = i >> 5, k = i & 31;
        s_wi[n * 40 + k] = __float2half(wih[i]);
        s_wh[n * 40 + k] = __float2half(whh[i]);
    }
    if (t < 96) { s_bi[t] = bih[t]; s_bh[t] = bhh[t]; }
    if (t >= 128 && t < 160) s_cb[t - 128] = convb[t - 128];
    __syncthreads();

    int w = t >> 5, lane = t & 31;
    int wb = blockIdx.x * 128 + w * 16;         // first row of this warp
    __half* sx = (__half*)s_buf[w];              // [16][40] fp16 x tile
    __half* sh = (__half*)(s_buf[w] + 1280);     // [16][40] fp16 hidden tile
    float*  so = (float*)s_buf[w];               // [16][36] fp32 out (reused)

    int r0 = lane >> 3, c4 = (lane & 7) * 4;
    float4 cb = *(float4*)&s_cb[c4];
    #pragma unroll
    for (int i = 0; i < 4; i++) {
        int row = r0 + i * 4;
        float4 av = *(const float4*)(g_agg + (size_t)(wb + row) * 32 + c4);
        *(__half2*)(sx + row * 40 + c4)     = __floats2half2_rn(fmaxf(av.x + cb.x, 0.f), fmaxf(av.y + cb.y, 0.f));
        *(__half2*)(sx + row * 40 + c4 + 2) = __floats2half2_rn(fmaxf(av.z + cb.z, 0.f), fmaxf(av.w + cb.w, 0.f));
        float4 hv = *(const float4*)(g_hidden + (size_t)(wb + row) * 32 + c4);
        *(__half2*)(sh + row * 40 + c4)     = __floats2half2_rn(hv.x, hv.y);
        *(__half2*)(sh + row * 40 + c4 + 2) = __floats2half2_rn(hv.z, hv.w);
    }
    __syncwarp();

    int g = lane >> 2, tg = lane & 3;
    unsigned af[2][4], hf[2][4];
    #pragma unroll
    for (int s = 0; s < 2; s++) {
        const __half* xr0 = sx + g * 40 + s * 16 + tg * 2;
        const __half* xr1 = sx + (g + 8) * 40 + s * 16 + tg * 2;
        af[s][0] = *(const unsigned*)(xr0);
        af[s][1] = *(const unsigned*)(xr1);
        af[s][2] = *(const unsigned*)(xr0 + 8);
        af[s][3] = *(const unsigned*)(xr1 + 8);
        const __half* hr0 = sh + g * 40 + s * 16 + tg * 2;
        const __half* hr1 = sh + (g + 8) * 40 + s * 16 + tg * 2;
        hf[s][0] = *(const unsigned*)(hr0);
        hf[s][1] = *(const unsigned*)(hr1);
        hf[s][2] = *(const unsigned*)(hr0 + 8);
        hf[s][3] = *(const unsigned*)(hr1 + 8);
    }
    __syncwarp();   // frags in regs; s_buf reusable for output staging

    float* outp = last ? d_out : g_hidden;

    #pragma unroll
    for (int cg = 0; cg < 4; cg++) {
        float xr[4] = {0,0,0,0}, xz[4] = {0,0,0,0}, xn[4] = {0,0,0,0};
        float hr[4] = {0,0,0,0}, hz[4] = {0,0,0,0}, hn[4] = {0,0,0,0};
        #pragma unroll
        for (int s = 0; s < 2; s++) {
            const __half* p;
            unsigned b0, b1;
            p = s_wi + (cg * 8 + g) * 40 + s * 16 + tg * 2;
            b0 = *(const unsigned*)p; b1 = *(const unsigned*)(p + 8);
            MMA_F32(xr[0], xr[1], xr[2], xr[3], af[s][0], af[s][1], af[s][2], af[s][3], b0, b1);
            p = s_wi + (32 + cg * 8 + g) * 40 + s * 16 + tg * 2;
            b0 = *(const unsigned*)p; b1 = *(const unsigned*)(p + 8);
            MMA_F32(xz[0], xz[1], xz[2], xz[3], af[s][0], af[s][1], af[s][2], af[s][3], b0, b1);
            p = s_wi + (64 + cg * 8 + g) * 40 + s * 16 + tg * 2;
            b0 = *(const unsigned*)p; b1 = *(const unsigned*)(p + 8);
            MMA_F32(xn[0], xn[1], xn[2], xn[3], af[s][0], af[s][1], af[s][2], af[s][3], b0, b1);
            p = s_wh + (cg * 8 + g) * 40 + s * 16 + tg * 2;
            b0 = *(const unsigned*)p; b1 = *(const unsigned*)(p + 8);
            MMA_F32(hr[0], hr[1], hr[2], hr[3], hf[s][0], hf[s][1], hf[s][2], hf[s][3], b0, b1);
            p = s_wh + (32 + cg * 8 + g) * 40 + s * 16 + tg * 2;
            b0 = *(const unsigned*)p; b1 = *(const unsigned*)(p + 8);
            MMA_F32(hz[0], hz[1], hz[2], hz[3], hf[s][0], hf[s][1], hf[s][2], hf[s][3], b0, b1);
            p = s_wh + (64 + cg * 8 + g) * 40 + s * 16 + tg * 2;
            b0 = *(const unsigned*)p; b1 = *(const unsigned*)(p + 8);
            MMA_F32(hn[0], hn[1], hn[2], hn[3], hf[s][0], hf[s][1], hf[s][2], hf[s][3], b0, b1);
        }
        int u0 = cg * 8 + tg * 2;
        float2 bir = *(float2*)&s_bi[u0],      bhr = *(float2*)&s_bh[u0];
        float2 biz = *(float2*)&s_bi[32 + u0], bhz = *(float2*)&s_bh[32 + u0];
        float2 bin = *(float2*)&s_bi[64 + u0], bhn = *(float2*)&s_bh[64 + u0];
        #pragma unroll
        for (int jp = 0; jp < 2; jp++) {          // jp=0: row g (j 0,1); jp=1: row g+8 (j 2,3)
            int rl = g + jp * 8;
            float2 hold = *(const float2*)(g_hidden + (size_t)(wb + rl) * 32 + u0);
            #pragma unroll
            for (int jj = 0; jj < 2; jj++) {
                int j = jp * 2 + jj;
                float bi_r = jj ? bir.y : bir.x, bh_r = jj ? bhr.y : bhr.x;
                float bi_z = jj ? biz.y : biz.x, bh_z = jj ? bhz.y : bhz.x;
                float bi_n = jj ? bin.y : bin.x, bh_n = jj ? bhn.y : bhn.x;
                float ho = jj ? hold.y : hold.x;
                float rv = sigmoidf_(xr[j] + hr[j] + bi_r + bh_r);
                float zv = sigmoidf_(xz[j] + hz[j] + bi_z + bh_z);
                float nv = tanhf(xn[j] + bi_n + rv * (hn[j] + bh_n));
                so[rl * 36 + u0 + jj] = (1.f - zv) * nv + zv * ho;
            }
        }
    }
    __syncwarp();

    float4 z4 = make_float4(0.f, 0.f, 0.f, 0.f);
    #pragma unroll
    for (int i = 0; i < 4; i++) {
        int row = r0 + i * 4;
        float4 val = *(float4*)(so + row * 36 + c4);
        *(float4*)(outp + (size_t)(wb + row) * 32 + c4) = val;
        *(float4*)(g_agg + (size_t)(wb + row) * 32 + c4) = z4;
    }
}

extern "C" void kernel_launch(void* const* d_in, const int* in_sizes, int n_in,
                              void* d_out, int out_size)
{
    const float* x     = (const float*)d_in[0];
    const float* rel   = (const float*)d_in[1];
    const float* pw1   = (const float*)d_in[2];
    const float* pb1   = (const float*)d_in[3];
    const float* pw2   = (const float*)d_in[4];
    const float* pb2   = (const float*)d_in[5];
    const float* ew1   = (const float*)d_in[6];
    const float* eb1   = (const float*)d_in[7];
    const float* ew2   = (const float*)d_in[8];
    const float* eb2   = (const float*)d_in[9];
    const float* convb = (const float*)d_in[10];
    const float* wih   = (const float*)d_in[11];
    const float* whh   = (const float*)d_in[12];
    const float* bih   = (const float*)d_in[13];
    const float* bhh   = (const float*)d_in[14];
    const int*   esrc  = (const int*)d_in[15];
    const int*   edst  = (const int*)d_in[16];
    float* out = (float*)d_out;

    proj_kernel<<<NB / 128, 128>>>(x, pw1, pb1, pw2, pb2);
    bt_prep_kernel<<<32768 / 256, 256>>>(ew2);
    we_gemm_kernel<<<dim3(8, N_EDGES / 128), 256>>>(rel, ew1, eb1, eb2);

    for (int s = 0; s < 3; s++) {
        msg_kernel<<<N_EDGES / 64, 256>>>(esrc, edst);
        gru_kernel<<<NB / 128, 256>>>(wih, whh, bih, bhh, convb, out, s == 2 ? 1 : 0);
    }
}

// round 9
// speedup vs baseline: 3.0686x; 1.3381x over previous
#include <cuda_runtime.h>
#include <cuda_fp16.h>

#define N_NODES 55296
#define N_EDGES 221184
#define NB      110592   // BATCH * N_NODES

// ---- dynamic smem layout for msgfused (bytes), 128 threads / 4 warps ----
// [0 .. 65536)        B fragments (4096 x uint4); reused as fp32 stage after mainloop
// [65536 .. 67584)    eb2 fp16 (1024 half)
// stage: per warp 64 rows * 36 floats = 9216 B, 4 warps = 36864 B (fits in B region)
// [67584 .. 86016)    feats fp16: per warp 64 rows * 36 halves = 4608 B
// [86016 .. 87040)    idx: per warp 64 ints
#define SM_EB    65536
#define SM_FEAT  67584
#define SM_IDX   86016
#define SM_TOTAL 87040

// Scratch (static device arrays: no allocation at launch time)
__device__ uint4  g_btp4[4096];                          // ew2^T frag-packed [tile nt][lane]
__device__ __half g_eb[1024];                            // eb2 fp16
__device__ uint4  g_af[(size_t)(N_EDGES / 16) * 2 * 32]; // A frags: [group][s][lane]
__device__ float  g_hidden[(size_t)NB * 32];
__device__ float  g_agg[(size_t)NB * 32];

__device__ __forceinline__ float sigmoidf_(float x) {
    return __fdividef(1.f, 1.f + __expf(-x));
}
__device__ __forceinline__ void red4(float* p, float a, float b, float c, float d) {
    asm volatile("red.global.add.v4.f32 [%0], {%1,%2,%3,%4};"
                 :: "l"(p), "f"(a), "f"(b), "f"(c), "f"(d) : "memory");
}
__device__ __forceinline__ void mma_f16(unsigned& c0, unsigned& c1,
    unsigned a0, unsigned a1, unsigned a2, unsigned a3, unsigned b0, unsigned b1) {
    asm volatile("mma.sync.aligned.m16n8k16.row.col.f16.f16.f16.f16 "
        "{%0,%1}, {%2,%3,%4,%5}, {%6,%7}, {%0,%1};"
        : "+r"(c0), "+r"(c1)
        : "r"(a0), "r"(a1), "r"(a2), "r"(a3), "r"(b0), "r"(b1));
}
#define MMA_F32(c0,c1,c2,c3,a0,a1,a2,a3,b0,b1) \
    asm volatile("mma.sync.aligned.m16n8k16.row.col.f32.f16.f16.f32 " \
        "{%0,%1,%2,%3}, {%4,%5,%6,%7}, {%8,%9}, {%0,%1,%2,%3};" \
        : "+f"(c0), "+f"(c1), "+f"(c2), "+f"(c3) \
        : "r"(a0), "r"(a1), "r"(a2), "r"(a3), "r"(b0), "r"(b1))

// ---------- node projection: h0 = ReLU(x@pw1+pb1)@pw2+pb2 ; also zero g_agg ----------
__global__ void __launch_bounds__(128) proj_kernel(
    const float* __restrict__ x,
    const float* __restrict__ pw1, const float* __restrict__ pb1,
    const float* __restrict__ pw2, const float* __restrict__ pb2)
{
    __shared__ float s_w1[1024], s_w2[1024], s_b1[32], s_b2[32];
    int t = threadIdx.x;
    for (int i = t; i < 1024; i += 128) { s_w1[i] = pw1[i]; s_w2[i] = pw2[i]; }
    if (t < 32) { s_b1[t] = pb1[t]; s_b2[t] = pb2[t]; }
    __syncthreads();

    int idx = blockIdx.x * 128 + t;

    float4 z = make_float4(0.f, 0.f, 0.f, 0.f);
    float4* zp = (float4*)(g_agg + (size_t)idx * 32);
    #pragma unroll
    for (int j = 0; j < 8; j++) zp[j] = z;

    float v[32];
    const float4* xp = (const float4*)(x + (size_t)idx * 32);
    #pragma unroll
    for (int i = 0; i < 8; i++) {
        float4 xv = xp[i];
        v[4*i+0] = xv.x; v[4*i+1] = xv.y; v[4*i+2] = xv.z; v[4*i+3] = xv.w;
    }
    float4 acc[8];
    #pragma unroll
    for (int j = 0; j < 8; j++) acc[j] = ((const float4*)s_b1)[j];
    #pragma unroll
    for (int c = 0; c < 32; c++) {
        float xv = v[c];
        #pragma unroll
        for (int j = 0; j < 8; j++) {
            float4 w = ((const float4*)s_w1)[c*8 + j];
            acc[j].x = fmaf(xv, w.x, acc[j].x);
            acc[j].y = fmaf(xv, w.y, acc[j].y);
            acc[j].z = fmaf(xv, w.z, acc[j].z);
            acc[j].w = fmaf(xv, w.w, acc[j].w);
        }
    }
    #pragma unroll
    for (int j = 0; j < 8; j++) {
        v[4*j+0] = fmaxf(acc[j].x, 0.f);
        v[4*j+1] = fmaxf(acc[j].y, 0.f);
        v[4*j+2] = fmaxf(acc[j].z, 0.f);
        v[4*j+3] = fmaxf(acc[j].w, 0.f);
    }
    #pragma unroll
    for (int j = 0; j < 8; j++) acc[j] = ((const float4*)s_b2)[j];
    #pragma unroll
    for (int c = 0; c < 32; c++) {
        float xv = v[c];
        #pragma unroll
        for (int j = 0; j < 8; j++) {
            float4 w = ((const float4*)s_w2)[c*8 + j];
            acc[j].x = fmaf(xv, w.x, acc[j].x);
            acc[j].y = fmaf(xv, w.y, acc[j].y);
            acc[j].z = fmaf(xv, w.z, acc[j].z);
            acc[j].w = fmaf(xv, w.w, acc[j].w);
        }
    }
    float4* op = (float4*)(g_hidden + (size_t)idx * 32);
    #pragma unroll
    for (int j = 0; j < 8; j++) op[j] = acc[j];
}

// ---------- prep B: frag-pack ew2^T + eb2 fp16 ----------
// Tile nt covers cols n = nt*8 .. nt*8+7. Lane (g=l>>2, tg=l&3) holds
// b0: B[k=tg*2, tg*2+1][n=nt*8+g]; b1: k+8; b2: k+16; b3: k+24.
__global__ void prep_b_kernel(const float* __restrict__ ew2, const float* __restrict__ eb2)
{
    int idx = blockIdx.x * 256 + threadIdx.x;   // [0, 4096)
    int nt = idx >> 5, lane = idx & 31;
    int g = lane >> 2, tg = lane & 3;
    int n = nt * 8 + g;
    int k0 = tg * 2;
    __half2 p0 = __floats2half2_rn(ew2[(k0+0)*1024 + n],  ew2[(k0+1)*1024 + n]);
    __half2 p1 = __floats2half2_rn(ew2[(k0+8)*1024 + n],  ew2[(k0+9)*1024 + n]);
    __half2 p2 = __floats2half2_rn(ew2[(k0+16)*1024 + n], ew2[(k0+17)*1024 + n]);
    __half2 p3 = __floats2half2_rn(ew2[(k0+24)*1024 + n], ew2[(k0+25)*1024 + n]);
    uint4 v;
    v.x = *(unsigned*)&p0; v.y = *(unsigned*)&p1;
    v.z = *(unsigned*)&p2; v.w = *(unsigned*)&p3;
    g_btp4[idx] = v;
    if (idx < 1024) g_eb[idx] = __float2half(eb2[idx]);
}

// ---------- prep A: A = ReLU(rel@ew1+eb1) fp16, frag-packed per 16-edge group ----------
__global__ void __launch_bounds__(256) prep_a_kernel(
    const float* __restrict__ rel,
    const float* __restrict__ ew1, const float* __restrict__ eb1)
{
    __shared__ float  s_w1[128], s_be[32];
    __shared__ __half s_ae[256][34];
    int t = threadIdx.x;
    if (t < 128) s_w1[t] = ew1[t];
    if (t >= 128 && t < 160) s_be[t - 128] = eb1[t - 128];
    __syncthreads();

    int e = blockIdx.x * 256 + t;
    float4 rp = __ldg((const float4*)rel + e);
    #pragma unroll
    for (int k = 0; k < 32; k++) {
        float a = s_be[k];
        a = fmaf(rp.x, s_w1[k],      a);
        a = fmaf(rp.y, s_w1[32 + k], a);
        a = fmaf(rp.z, s_w1[64 + k], a);
        a = fmaf(rp.w, s_w1[96 + k], a);
        s_ae[t][k] = __float2half(fmaxf(a, 0.f));
    }
    __syncthreads();

    int w = t >> 5, lane = t & 31;
    int g = lane >> 2, tg = lane & 3;
    #pragma unroll
    for (int gi = 0; gi < 2; gi++) {
        int grp = w * 2 + gi;
        int eb_ = grp * 16;
        size_t G = (size_t)blockIdx.x * 16 + grp;
        #pragma unroll
        for (int s = 0; s < 2; s++) {
            int k0 = s * 16 + tg * 2;
            uint4 v;
            v.x = *(unsigned*)&s_ae[eb_ + g][k0];
            v.y = *(unsigned*)&s_ae[eb_ + g + 8][k0];
            v.z = *(unsigned*)&s_ae[eb_ + g][k0 + 8];
            v.w = *(unsigned*)&s_ae[eb_ + g + 8][k0 + 8];
            g_af[(G * 2 + s) * 32 + lane] = v;
        }
    }
}

// ---------- fused message pass: We recomputed on the fly via tensor cores ----------
// 128 thr / 4 warps, 32 edges per warp. Block-resident B (ew2^T frags) in smem.
__global__ void __launch_bounds__(128) msgfused_kernel(
    const int* __restrict__ esrc, const int* __restrict__ edst)
{
    extern __shared__ char smem[];
    uint4*  s_b4 = (uint4*)smem;
    __half* s_eb = (__half*)(smem + SM_EB);
    int t = threadIdx.x, w = t >> 5, lane = t & 31;
    __half* s_ft  = (__half*)(smem + SM_FEAT + w * 4608);  // [64 rows (e*2+b)][36 halves]
    int*    s_idx = (int*)(smem + SM_IDX + w * 256);
    float*  s_st  = (float*)(smem + w * 9216);             // stage: [64 rows][36 floats]

    // cooperative: B frags + eb2
    #pragma unroll
    for (int i = 0; i < 32; i++) s_b4[t + i * 128] = g_btp4[t + i * 128];
    ((uint4*)s_eb)[t] = ((const uint4*)g_eb)[t];

    int e0 = blockIdx.x * 128 + w * 32;
    s_idx[lane]      = esrc[e0 + lane];
    s_idx[32 + lane] = edst[e0 + lane];
    __syncwarp();

    // gather src feats: 64 rows (e*2+b) x 32 h, fp32 -> fp16 smem
    #pragma unroll
    for (int i = 0; i < 16; i++) {
        int u = lane + 32 * i;            // [0,512)
        int r = u >> 3, q = u & 7;        // r = e*2+b, q = float4 chunk
        int e = r >> 1, b = r & 1;
        int src = s_idx[e];
        float4 v = __ldg((const float4*)(g_hidden + ((size_t)b * N_NODES + src) * 32 + q * 4));
        __half2 h01 = __floats2half2_rn(v.x, v.y);
        __half2 h23 = __floats2half2_rn(v.z, v.w);
        *(uint2*)(s_ft + r * 36 + q * 4) = make_uint2(*(unsigned*)&h01, *(unsigned*)&h23);
    }

    // A fragments for this warp's 2 tiles of 16 edges
    size_t G0 = (size_t)(e0 >> 4);
    uint4 a0s0 = __ldg(&g_af[(G0 * 2 + 0) * 32 + lane]);
    uint4 a0s1 = __ldg(&g_af[(G0 * 2 + 1) * 32 + lane]);
    uint4 a1s0 = __ldg(&g_af[((G0 + 1) * 2 + 0) * 32 + lane]);
    uint4 a1s1 = __ldg(&g_af[((G0 + 1) * 2 + 1) * 32 + lane]);

    __syncthreads();   // B/eb visible; feats (warp-local) done

    int g = lane >> 2, tg = lane & 3;
    // acc[ei][b][m*2+c]: edge = g + ei*8 (local), output o = m*8 + tg*2 + c
    float acc[4][2][8];
    #pragma unroll
    for (int ei = 0; ei < 4; ei++)
        #pragma unroll
        for (int b = 0; b < 2; b++)
            #pragma unroll
            for (int m = 0; m < 8; m++) acc[ei][b][m] = 0.f;

    for (int j = 0; j < 8; j++) {          // h-quads: h = j*4 + p*2 + hl
        #pragma unroll
        for (int p = 0; p < 2; p++) {
            // feats for h-pair (j*4+p*2, +1), all 4 edge rows, both batches
            float f[4][2][2];
            #pragma unroll
            for (int ei = 0; ei < 4; ei++) {
                int e = g + ei * 8;
                #pragma unroll
                for (int b = 0; b < 2; b++) {
                    __half2 hp = *(__half2*)(s_ft + (e * 2 + b) * 36 + j * 4 + p * 2);
                    float2 fp = __half22float2(hp);
                    f[ei][b][0] = fp.x; f[ei][b][1] = fp.y;
                }
            }
            #pragma unroll
            for (int nn = 0; nn < 8; nn++) {
                int jt = j * 16 + p * 8 + nn;      // global 8-col tile, h = jt>>2, m = jt&3
                uint4 B = s_b4[jt * 32 + lane];
                __half2 ebp = *(__half2*)(s_eb + jt * 8 + tg * 2);
                unsigned hc0 = 0u, hc1 = 0u, hc2 = 0u, hc3 = 0u;
                mma_f16(hc0, hc1, a0s0.x, a0s0.y, a0s0.z, a0s0.w, B.x, B.y);
                mma_f16(hc0, hc1, a0s1.x, a0s1.y, a0s1.z, a0s1.w, B.z, B.w);
                mma_f16(hc2, hc3, a1s0.x, a1s0.y, a1s0.z, a1s0.w, B.x, B.y);
                mma_f16(hc2, hc3, a1s1.x, a1s1.y, a1s1.z, a1s1.w, B.z, B.w);
                float2 v0 = __half22float2(__hadd2(*(__half2*)&hc0, ebp));
                float2 v1 = __half22float2(__hadd2(*(__half2*)&hc1, ebp));
                float2 v2 = __half22float2(__hadd2(*(__half2*)&hc2, ebp));
                float2 v3 = __half22float2(__hadd2(*(__half2*)&hc3, ebp));
                const int hl = nn >> 2;            // which h of the pair
                const int m = nn & 3;              // o-block within h
                acc[0][0][m*2+0] = fmaf(f[0][0][hl], v0.x, acc[0][0][m*2+0]);
                acc[0][0][m*2+1] = fmaf(f[0][0][hl], v0.y, acc[0][0][m*2+1]);
                acc[0][1][m*2+0] = fmaf(f[0][1][hl], v0.x, acc[0][1][m*2+0]);
                acc[0][1][m*2+1] = fmaf(f[0][1][hl], v0.y, acc[0][1][m*2+1]);
                acc[1][0][m*2+0] = fmaf(f[1][0][hl], v1.x, acc[1][0][m*2+0]);
                acc[1][0][m*2+1] = fmaf(f[1][0][hl], v1.y, acc[1][0][m*2+1]);
                acc[1][1][m*2+0] = fmaf(f[1][1][hl], v1.x, acc[1][1][m*2+0]);
                acc[1][1][m*2+1] = fmaf(f[1][1][hl], v1.y, acc[1][1][m*2+1]);
                acc[2][0][m*2+0] = fmaf(f[2][0][hl], v2.x, acc[2][0][m*2+0]);
                acc[2][0][m*2+1] = fmaf(f[2][0][hl], v2.y, acc[2][0][m*2+1]);
                acc[2][1][m*2+0] = fmaf(f[2][1][hl], v2.x, acc[2][1][m*2+0]);
                acc[2][1][m*2+1] = fmaf(f[2][1][hl], v2.y, acc[2][1][m*2+1]);
                acc[3][0][m*2+0] = fmaf(f[3][0][hl], v3.x, acc[3][0][m*2+0]);
                acc[3][0][m*2+1] = fmaf(f[3][0][hl], v3.y, acc[3][0][m*2+1]);
                acc[3][1][m*2+0] = fmaf(f[3][1][hl], v3.x, acc[3][1][m*2+0]);
                acc[3][1][m*2+1] = fmaf(f[3][1][hl], v3.y, acc[3][1][m*2+1]);
            }
        }
    }
    __syncthreads();   // everyone done reading s_b4/s_eb -> reuse as stage

    // stage acc as [row = e*2+b][o] fp32
    #pragma unroll
    for (int ei = 0; ei < 4; ei++) {
        int e = g + ei * 8;
        #pragma unroll
        for (int b = 0; b < 2; b++) {
            #pragma unroll
            for (int m = 0; m < 4; m++) {
                *(float2*)(s_st + (e * 2 + b) * 36 + m * 8 + tg * 2) =
                    make_float2(acc[ei][b][m*2], acc[ei][b][m*2+1]);
            }
        }
    }
    __syncwarp();

    // coalesced scatter via red.v4
    #pragma unroll
    for (int i = 0; i < 16; i++) {
        int u = lane + 32 * i;            // [0,512)
        int e = u >> 4, b = (u >> 3) & 1, q = u & 7;
        float4 v = *(float4*)(s_st + (e * 2 + b) * 36 + q * 4);
        int dst = s_idx[32 + e];
        red4(g_agg + ((size_t)b * N_NODES + dst) * 32 + q * 4, v.x, v.y, v.z, v.w);
    }
}

// ---------- GRU via tensor cores (unchanged, validated) ----------
__global__ void __launch_bounds__(256) gru_kernel(
    const float* __restrict__ wih, const float* __restrict__ whh,
    const float* __restrict__ bih, const float* __restrict__ bhh,
    const float* __restrict__ convb,
    float* __restrict__ d_out, int last)
{
    __shared__ __half s_wi[96 * 40];
    __shared__ __half s_wh[96 * 40];
    __shared__ float s_bi[96], s_bh[96], s_cb[32];
    __shared__ __align__(16) char s_buf[8][2880];

    int t = threadIdx.x;
    for (int i = t; i < 3072; i += 256) {
        int n = i >> 5, k = i & 31;
        s_wi[n * 40 + k] = __float2half(wih[i]);
        s_wh[n * 40 + k] = __float2half(whh[i]);
    }
    if (t < 96) { s_bi[t] = bih[t]; s_bh[t] = bhh[t]; }
    if (t >= 128 && t < 160) s_cb[t - 128] = convb[t - 128];
    __syncthreads();

    int w = t >> 5, lane = t & 31;
    int wb = blockIdx.x * 128 + w * 16;
    __half* sx = (__half*)s_buf[w];
    __half* sh = (__half*)(s_buf[w] + 1280);
    float*  so = (float*)s_buf[w];

    int r0 = lane >> 3, c4 = (lane & 7) * 4;
    float4 cb = *(float4*)&s_cb[c4];
    #pragma unroll
    for (int i = 0; i < 4; i++) {
        int row = r0 + i * 4;
        float4 av = *(const float4*)(g_agg + (size_t)(wb + row) * 32 + c4);
        *(__half2*)(sx + row * 40 + c4)     = __floats2half2_rn(fmaxf(av.x + cb.x, 0.f), fmaxf(av.y + cb.y, 0.f));
        *(__half2*)(sx + row * 40 + c4 + 2) = __floats2half2_rn(fmaxf(av.z + cb.z, 0.f), fmaxf(av.w + cb.w, 0.f));
        float4 hv = *(const float4*)(g_hidden + (size_t)(wb + row) * 32 + c4);
        *(__half2*)(sh + row * 40 + c4)     = __floats2half2_rn(hv.x, hv.y);
        *(__half2*)(sh + row * 40 + c4 + 2) = __floats2half2_rn(hv.z, hv.w);
    }
    __syncwarp();

    int g = lane >> 2, tg = lane & 3;
    unsigned af[2][4], hf[2][4];
    #pragma unroll
    for (int s = 0; s < 2; s++) {
        const __half* xr0 = sx + g * 40 + s * 16 + tg * 2;
        const __half* xr1 = sx + (g + 8) * 40 + s * 16 + tg * 2;
        af[s][0] = *(const unsigned*)(xr0);
        af[s][1] = *(const unsigned*)(xr1);
        af[s][2] = *(const unsigned*)(xr0 + 8);
        af[s][3] = *(const unsigned*)(xr1 + 8);
        const __half* hr0 = sh + g * 40 + s * 16 + tg * 2;
        const __half* hr1 = sh + (g + 8) * 40 + s * 16 + tg * 2;
        hf[s][0] = *(const unsigned*)(hr0);
        hf[s][1] = *(const unsigned*)(hr1);
        hf[s][2] = *(const unsigned*)(hr0 + 8);
        hf[s][3] = *(const unsigned*)(hr1 + 8);
    }
    __syncwarp();

    float* outp = last ? d_out : g_hidden;

    #pragma unroll
    for (int cg = 0; cg < 4; cg++) {
        float xr[4] = {0,0,0,0}, xz[4] = {0,0,0,0}, xn[4] = {0,0,0,0};
        float hr[4] = {0,0,0,0}, hz[4] = {0,0,0,0}, hn[4] = {0,0,0,0};
        #pragma unroll
        for (int s = 0; s < 2; s++) {
            const __half* p;
            unsigned b0, b1;
            p = s_wi + (cg * 8 + g) * 40 + s * 16 + tg * 2;
            b0 = *(const unsigned*)p; b1 = *(const unsigned*)(p + 8);
            MMA_F32(xr[0], xr[1], xr[2], xr[3], af[s][0], af[s][1], af[s][2], af[s][3], b0, b1);
            p = s_wi + (32 + cg * 8 + g) * 40 + s * 16 + tg * 2;
            b0 = *(const unsigned*)p; b1 = *(const unsigned*)(p + 8);
            MMA_F32(xz[0], xz[1], xz[2], xz[3], af[s][0], af[s][1], af[s][2], af[s][3], b0, b1);
            p = s_wi + (64 + cg * 8 + g) * 40 + s * 16 + tg * 2;
            b0 = *(const unsigned*)p; b1 = *(const unsigned*)(p + 8);
            MMA_F32(xn[0], xn[1], xn[2], xn[3], af[s][0], af[s][1], af[s][2], af[s][3], b0, b1);
            p = s_wh + (cg * 8 + g) * 40 + s * 16 + tg * 2;
            b0 = *(const unsigned*)p; b1 = *(const unsigned*)(p + 8);
            MMA_F32(hr[0], hr[1], hr[2], hr[3], hf[s][0], hf[s][1], hf[s][2], hf[s][3], b0, b1);
            p = s_wh + (32 + cg * 8 + g) * 40 + s * 16 + tg * 2;
            b0 = *(const unsigned*)p; b1 = *(const unsigned*)(p + 8);
            MMA_F32(hz[0], hz[1], hz[2], hz[3], hf[s][0], hf[s][1], hf[s][2], hf[s][3], b0, b1);
            p = s_wh + (64 + cg * 8 + g) * 40 + s * 16 + tg * 2;
            b0 = *(const unsigned*)p; b1 = *(const unsigned*)(p + 8);
            MMA_F32(hn[0], hn[1], hn[2], hn[3], hf[s][0], hf[s][1], hf[s][2], hf[s][3], b0, b1);
        }
        int u0 = cg * 8 + tg * 2;
        float2 bir = *(float2*)&s_bi[u0],      bhr = *(float2*)&s_bh[u0];
        float2 biz = *(float2*)&s_bi[32 + u0], bhz = *(float2*)&s_bh[32 + u0];
        float2 bin = *(float2*)&s_bi[64 + u0], bhn = *(float2*)&s_bh[64 + u0];
        #pragma unroll
        for (int jp = 0; jp < 2; jp++) {
            int rl = g + jp * 8;
            float2 hold = *(const float2*)(g_hidden + (size_t)(wb + rl) * 32 + u0);
            #pragma unroll
            for (int jj = 0; jj < 2; jj++) {
                int j = jp * 2 + jj;
                float bi_r = jj ? bir.y : bir.x, bh_r = jj ? bhr.y : bhr.x;
                float bi_z = jj ? biz.y : biz.x, bh_z = jj ? bhz.y : bhz.x;
                float bi_n = jj ? bin.y : bin.x, bh_n = jj ? bhn.y : bhn.x;
                float ho = jj ? hold.y : hold.x;
                float rv = sigmoidf_(xr[j] + hr[j] + bi_r + bh_r);
                float zv = sigmoidf_(xz[j] + hz[j] + bi_z + bh_z);
                float nv = tanhf(xn[j] + bi_n + rv * (hn[j] + bh_n));
                so[rl * 36 + u0 + jj] = (1.f - zv) * nv + zv * ho;
            }
        }
    }
    __syncwarp();

    float4 z4 = make_float4(0.f, 0.f, 0.f, 0.f);
    #pragma unroll
    for (int i = 0; i < 4; i++) {
        int row = r0 + i * 4;
        float4 val = *(float4*)(so + row * 36 + c4);
        *(float4*)(outp + (size_t)(wb + row) * 32 + c4) = val;
        *(float4*)(g_agg + (size_t)(wb + row) * 32 + c4) = z4;
    }
}

extern "C" void kernel_launch(void* const* d_in, const int* in_sizes, int n_in,
                              void* d_out, int out_size)
{
    const float* x     = (const float*)d_in[0];
    const float* rel   = (const float*)d_in[1];
    const float* pw1   = (const float*)d_in[2];
    const float* pb1   = (const float*)d_in[3];
    const float* pw2   = (const float*)d_in[4];
    const float* pb2   = (const float*)d_in[5];
    const float* ew1   = (const float*)d_in[6];
    const float* eb1   = (const float*)d_in[7];
    const float* ew2   = (const float*)d_in[8];
    const float* eb2   = (const float*)d_in[9];
    const float* convb = (const float*)d_in[10];
    const float* wih   = (const float*)d_in[11];
    const float* whh   = (const float*)d_in[12];
    const float* bih   = (const float*)d_in[13];
    const float* bhh   = (const float*)d_in[14];
    const int*   esrc  = (const int*)d_in[15];
    const int*   edst  = (const int*)d_in[16];
    float* out = (float*)d_out;

    cudaFuncSetAttribute(msgfused_kernel,
                         cudaFuncAttributeMaxDynamicSharedMemorySize, SM_TOTAL);

    proj_kernel<<<NB / 128, 128>>>(x, pw1, pb1, pw2, pb2);
    prep_b_kernel<<<4096 / 256, 256>>>(ew2, eb2);
    prep_a_kernel<<<N_EDGES / 256, 256>>>(rel, ew1, eb1);

    for (int s = 0; s < 3; s++) {
        msgfused_kernel<<<N_EDGES / 128, 128, SM_TOTAL>>>(esrc, edst);
        gru_kernel<<<NB / 128, 256>>>(wih, whh, bih, bhh, convb, out, s == 2 ? 1 : 0);
    }
}

// round 12
// speedup vs baseline: 3.6784x; 1.1987x over previous
#include <cuda_runtime.h>
#include <cuda_fp16.h>

#define N_NODES 55296
#define N_EDGES 221184
#define NB      110592   // BATCH * N_NODES

typedef unsigned long long ull;

// ---- dynamic smem layout for msgfused (bytes), 256 threads / 8 warps, 16 edges/warp ----
// [0 .. 65536)        B fragments (4096 x uint4); reused as fp32 stage after mainloop
//                     stage: per warp 32 rows * 36 floats = 4608 B, 8 warps = 36864 B (fits)
// [65536 .. 67584)    eb2 fp16 (1024 half)
// [67584 .. 86016)    feats fp16: per warp 32 rows * 36 halves = 2304 B
// [86016 .. 87040)    idx: per warp 16 src + 16 dst ints = 128 B
#define SM_EB    65536
#define SM_FEAT  67584
#define SM_IDX   86016
#define SM_TOTAL 87040

// Scratch (static device arrays: no allocation at launch time)
__device__ uint4  g_btp4[4096];                          // ew2^T frag-packed [tile nt][lane]
__device__ __half g_eb[1024];                            // eb2 fp16
__device__ uint4  g_af[(size_t)(N_EDGES / 16) * 2 * 32]; // A frags: [group][s][lane]
__device__ float  g_hidden[(size_t)NB * 32];
__device__ float  g_agg[(size_t)NB * 32];

__device__ __forceinline__ float sigmoidf_(float x) {
    return __fdividef(1.f, 1.f + __expf(-x));
}
__device__ __forceinline__ void red4(float* p, float a, float b, float c, float d) {
    asm volatile("red.global.add.v4.f32 [%0], {%1,%2,%3,%4};"
                 :: "l"(p), "f"(a), "f"(b), "f"(c), "f"(d) : "memory");
}
__device__ __forceinline__ ull pack2(float lo, float hi) {
    ull v; asm("mov.b64 %0, {%1, %2};" : "=l"(v) : "f"(lo), "f"(hi)); return v;
}
__device__ __forceinline__ float2 unpack2(ull v) {
    float2 f; asm("mov.b64 {%0, %1}, %2;" : "=f"(f.x), "=f"(f.y) : "l"(v)); return f;
}
__device__ __forceinline__ void fma2(ull& d, ull a, ull b) {
    asm("fma.rn.f32x2 %0, %1, %2, %0;" : "+l"(d) : "l"(a), "l"(b));
}
__device__ __forceinline__ void mma_f16(unsigned& c0, unsigned& c1,
    unsigned a0, unsigned a1, unsigned a2, unsigned a3, unsigned b0, unsigned b1) {
    asm volatile("mma.sync.aligned.m16n8k16.row.col.f16.f16.f16.f16 "
        "{%0,%1}, {%2,%3,%4,%5}, {%6,%7}, {%0,%1};"
        : "+r"(c0), "+r"(c1)
        : "r"(a0), "r"(a1), "r"(a2), "r"(a3), "r"(b0), "r"(b1));
}
#define MMA_F32(c0,c1,c2,c3,a0,a1,a2,a3,b0,b1) \
    asm volatile("mma.sync.aligned.m16n8k16.row.col.f32.f16.f16.f32 " \
        "{%0,%1,%2,%3}, {%4,%5,%6,%7}, {%8,%9}, {%0,%1,%2,%3};" \
        : "+f"(c0), "+f"(c1), "+f"(c2), "+f"(c3) \
        : "r"(a0), "r"(a1), "r"(a2), "r"(a3), "r"(b0), "r"(b1))

// ---------- node projection: h0 = ReLU(x@pw1+pb1)@pw2+pb2 ; also zero g_agg ----------
__global__ void __launch_bounds__(128) proj_kernel(
    const float* __restrict__ x,
    const float* __restrict__ pw1, const float* __restrict__ pb1,
    const float* __restrict__ pw2, const float* __restrict__ pb2)
{
    __shared__ float s_w1[1024], s_w2[1024], s_b1[32], s_b2[32];
    int t = threadIdx.x;
    for (int i = t; i < 1024; i += 128) { s_w1[i] = pw1[i]; s_w2[i] = pw2[i]; }
    if (t < 32) { s_b1[t] = pb1[t]; s_b2[t] = pb2[t]; }
    __syncthreads();

    int idx = blockIdx.x * 128 + t;

    float4 z = make_float4(0.f, 0.f, 0.f, 0.f);
    float4* zp = (float4*)(g_agg + (size_t)idx * 32);
    #pragma unroll
    for (int j = 0; j < 8; j++) zp[j] = z;

    float v[32];
    const float4* xp = (const float4*)(x + (size_t)idx * 32);
    #pragma unroll
    for (int i = 0; i < 8; i++) {
        float4 xv = xp[i];
        v[4*i+0] = xv.x; v[4*i+1] = xv.y; v[4*i+2] = xv.z; v[4*i+3] = xv.w;
    }
    float4 acc[8];
    #pragma unroll
    for (int j = 0; j < 8; j++) acc[j] = ((const float4*)s_b1)[j];
    #pragma unroll
    for (int c = 0; c < 32; c++) {
        float xv = v[c];
        #pragma unroll
        for (int j = 0; j < 8; j++) {
            float4 w = ((const float4*)s_w1)[c*8 + j];
            acc[j].x = fmaf(xv, w.x, acc[j].x);
            acc[j].y = fmaf(xv, w.y, acc[j].y);
            acc[j].z = fmaf(xv, w.z, acc[j].z);
            acc[j].w = fmaf(xv, w.w, acc[j].w);
        }
    }
    #pragma unroll
    for (int j = 0; j < 8; j++) {
        v[4*j+0] = fmaxf(acc[j].x, 0.f);
        v[4*j+1] = fmaxf(acc[j].y, 0.f);
        v[4*j+2] = fmaxf(acc[j].z, 0.f);
        v[4*j+3] = fmaxf(acc[j].w, 0.f);
    }
    #pragma unroll
    for (int j = 0; j < 8; j++) acc[j] = ((const float4*)s_b2)[j];
    #pragma unroll
    for (int c = 0; c < 32; c++) {
        float xv = v[c];
        #pragma unroll
        for (int j = 0; j < 8; j++) {
            float4 w = ((const float4*)s_w2)[c*8 + j];
            acc[j].x = fmaf(xv, w.x, acc[j].x);
            acc[j].y = fmaf(xv, w.y, acc[j].y);
            acc[j].z = fmaf(xv, w.z, acc[j].z);
            acc[j].w = fmaf(xv, w.w, acc[j].w);
        }
    }
    float4* op = (float4*)(g_hidden + (size_t)idx * 32);
    #pragma unroll
    for (int j = 0; j < 8; j++) op[j] = acc[j];
}

// ---------- prep B: frag-pack ew2^T + eb2 fp16 ----------
__global__ void prep_b_kernel(const float* __restrict__ ew2, const float* __restrict__ eb2)
{
    int idx = blockIdx.x * 256 + threadIdx.x;   // [0, 4096)
    int nt = idx >> 5, lane = idx & 31;
    int g = lane >> 2, tg = lane & 3;
    int n = nt * 8 + g;
    int k0 = tg * 2;
    __half2 p0 = __floats2half2_rn(ew2[(k0+0)*1024 + n],  ew2[(k0+1)*1024 + n]);
    __half2 p1 = __floats2half2_rn(ew2[(k0+8)*1024 + n],  ew2[(k0+9)*1024 + n]);
    __half2 p2 = __floats2half2_rn(ew2[(k0+16)*1024 + n], ew2[(k0+17)*1024 + n]);
    __half2 p3 = __floats2half2_rn(ew2[(k0+24)*1024 + n], ew2[(k0+25)*1024 + n]);
    uint4 v;
    v.x = *(unsigned*)&p0; v.y = *(unsigned*)&p1;
    v.z = *(unsigned*)&p2; v.w = *(unsigned*)&p3;
    g_btp4[idx] = v;
    if (idx < 1024) g_eb[idx] = __float2half(eb2[idx]);
}

// ---------- prep A: A = ReLU(rel@ew1+eb1) fp16, frag-packed per 16-edge group ----------
__global__ void __launch_bounds__(256) prep_a_kernel(
    const float* __restrict__ rel,
    const float* __restrict__ ew1, const float* __restrict__ eb1)
{
    __shared__ float  s_w1[128], s_be[32];
    __shared__ __half s_ae[256][34];
    int t = threadIdx.x;
    if (t < 128) s_w1[t] = ew1[t];
    if (t >= 128 && t < 160) s_be[t - 128] = eb1[t - 128];
    __syncthreads();

    int e = blockIdx.x * 256 + t;
    float4 rp = __ldg((const float4*)rel + e);
    #pragma unroll
    for (int k = 0; k < 32; k++) {
        float a = s_be[k];
        a = fmaf(rp.x, s_w1[k],      a);
        a = fmaf(rp.y, s_w1[32 + k], a);
        a = fmaf(rp.z, s_w1[64 + k], a);
        a = fmaf(rp.w, s_w1[96 + k], a);
        s_ae[t][k] = __float2half(fmaxf(a, 0.f));
    }
    __syncthreads();

    int w = t >> 5, lane = t & 31;
    int g = lane >> 2, tg = lane & 3;
    #pragma unroll
    for (int gi = 0; gi < 2; gi++) {
        int grp = w * 2 + gi;
        int eb_ = grp * 16;
        size_t G = (size_t)blockIdx.x * 16 + grp;
        #pragma unroll
        for (int s = 0; s < 2; s++) {
            int k0 = s * 16 + tg * 2;
            uint4 v;
            v.x = *(unsigned*)&s_ae[eb_ + g][k0];
            v.y = *(unsigned*)&s_ae[eb_ + g + 8][k0];
            v.z = *(unsigned*)&s_ae[eb_ + g][k0 + 8];
            v.w = *(unsigned*)&s_ae[eb_ + g + 8][k0 + 8];
            g_af[(G * 2 + s) * 32 + lane] = v;
        }
    }
}

// ---------- fused message pass: We recomputed via tensor cores; 16 edges/warp ----------
// 256 thr / 8 warps; 128 edges per block. Block-resident B (ew2^T frags) in smem.
__global__ void __launch_bounds__(256, 2) msgfused_kernel(
    const int* __restrict__ esrc, const int* __restrict__ edst)
{
    extern __shared__ char smem[];
    uint4*  s_b4 = (uint4*)smem;
    __half* s_eb = (__half*)(smem + SM_EB);
    int t = threadIdx.x, w = t >> 5, lane = t & 31;
    __half* s_ft  = (__half*)(smem + SM_FEAT + w * 2304);  // [32 rows (e*2+b)][36 halves]
    int*    s_idx = (int*)(smem + SM_IDX + w * 128);       // [16 src][16 dst]
    float*  s_st  = (float*)(smem + w * 4608);             // stage: [32 rows][36 floats]

    // cooperative: B frags + eb2
    #pragma unroll
    for (int i = 0; i < 16; i++) s_b4[t + i * 256] = g_btp4[t + i * 256];
    if (t < 128) ((uint4*)s_eb)[t] = ((const uint4*)g_eb)[t];

    int e0 = blockIdx.x * 128 + w * 16;
    if (lane < 16)      s_idx[lane] = esrc[e0 + lane];
    else                s_idx[lane] = edst[e0 + lane - 16];
    __syncwarp();

    // gather src feats: 32 rows (e*2+b) x 32 h, fp32 -> fp16 smem
    #pragma unroll
    for (int i = 0; i < 8; i++) {
        int u = lane + 32 * i;            // [0,256)
        int r = u >> 3, q = u & 7;        // r = e*2+b, q = float4 chunk
        int e = r >> 1, b = r & 1;
        int src = s_idx[e];
        float4 v = __ldg((const float4*)(g_hidden + ((size_t)b * N_NODES + src) * 32 + q * 4));
        __half2 h01 = __floats2half2_rn(v.x, v.y);
        __half2 h23 = __floats2half2_rn(v.z, v.w);
        *(uint2*)(s_ft + r * 36 + q * 4) = make_uint2(*(unsigned*)&h01, *(unsigned*)&h23);
    }

    // A fragments for this warp's 16-edge tile
    size_t G0 = (size_t)(e0 >> 4);
    uint4 as0 = __ldg(&g_af[(G0 * 2 + 0) * 32 + lane]);
    uint4 as1 = __ldg(&g_af[(G0 * 2 + 1) * 32 + lane]);

    __syncthreads();   // B/eb visible; feats (warp-local) done

    int g = lane >> 2, tg = lane & 3;
    // acc2[ei][b][m]: edge = g + ei*8, output pair o = {m*8+tg*2, +1}
    ull acc2[2][2][4];
    #pragma unroll
    for (int ei = 0; ei < 2; ei++)
        #pragma unroll
        for (int b = 0; b < 2; b++)
            #pragma unroll
            for (int m = 0; m < 4; m++) acc2[ei][b][m] = 0ull;

    for (int j = 0; j < 8; j++) {          // h = j*4 + p*2 + hl
        #pragma unroll
        for (int p = 0; p < 2; p++) {
            // broadcast feature packs for this h-pair (hoisted over 8 tiles)
            ull fp[2][2][2];   // [ei][b][hl], value duplicated in both halves
            #pragma unroll
            for (int ei = 0; ei < 2; ei++) {
                int e = g + ei * 8;
                #pragma unroll
                for (int b = 0; b < 2; b++) {
                    __half2 hp = *(__half2*)(s_ft + (e * 2 + b) * 36 + j * 4 + p * 2);
                    float2 ff = __half22float2(hp);
                    fp[ei][b][0] = pack2(ff.x, ff.x);
                    fp[ei][b][1] = pack2(ff.y, ff.y);
                }
            }
            #pragma unroll
            for (int nn = 0; nn < 8; nn++) {
                int jt = j * 16 + p * 8 + nn;      // 8-col tile: h = jt>>2, m = jt&3
                uint4 B = s_b4[jt * 32 + lane];
                __half2 ebp = *(__half2*)(s_eb + jt * 8 + tg * 2);
                unsigned hc0 = 0u, hc1 = 0u;
                mma_f16(hc0, hc1, as0.x, as0.y, as0.z, as0.w, B.x, B.y);
                mma_f16(hc0, hc1, as1.x, as1.y, as1.z, as1.w, B.z, B.w);
                float2 v0 = __half22float2(__hadd2(*(__half2*)&hc0, ebp));
                float2 v1 = __half22float2(__hadd2(*(__half2*)&hc1, ebp));
                ull v0p = pack2(v0.x, v0.y);
                ull v1p = pack2(v1.x, v1.y);
                const int hl = nn >> 2;
                const int m = nn & 3;
                fma2(acc2[0][0][m], fp[0][0][hl], v0p);
                fma2(acc2[0][1][m], fp[0][1][hl], v0p);
                fma2(acc2[1][0][m], fp[1][0][hl], v1p);
                fma2(acc2[1][1][m], fp[1][1][hl], v1p);
            }
        }
    }
    __syncthreads();   // everyone done reading s_b4/s_eb -> reuse as stage

    // stage acc as [row = e*2+b][o] fp32
    #pragma unroll
    for (int ei = 0; ei < 2; ei++) {
        int e = g + ei * 8;
        #pragma unroll
        for (int b = 0; b < 2; b++) {
            #pragma unroll
            for (int m = 0; m < 4; m++) {
                float2 pr = unpack2(acc2[ei][b][m]);
                *(float2*)(s_st + (e * 2 + b) * 36 + m * 8 + tg * 2) = pr;
            }
        }
    }
    __syncwarp();

    // coalesced scatter via red.v4
    #pragma unroll
    for (int i = 0; i < 8; i++) {
        int u = lane + 32 * i;            // [0,256)
        int r = u >> 3, q = u & 7;
        int e = r >> 1, b = r & 1;
        float4 v = *(float4*)(s_st + r * 36 + q * 4);
        int dst = s_idx[16 + e];
        red4(g_agg + ((size_t)b * N_NODES + dst) * 32 + q * 4, v.x, v.y, v.z, v.w);
    }
}

// ---------- GRU via tensor cores (unchanged, validated) ----------
__global__ void __launch_bounds__(256) gru_kernel(
    const float* __restrict__ wih, const float* __restrict__ whh,
    const float* __restrict__ bih, const float* __restrict__ bhh,
    const float* __restrict__ convb,
    float* __restrict__ d_out, int last)
{
    __shared__ __half s_wi[96 * 40];
    __shared__ __half s_wh[96 * 40];
    __shared__ float s_bi[96], s_bh[96], s_cb[32];
    __shared__ __align__(16) char s_buf[8][2880];

    int t = threadIdx.x;
    for (int i = t; i < 3072; i += 256) {
        int n = i >> 5, k = i & 31;
        s_wi[n * 40 + k] = __float2half(wih[i]);
        s_wh[n * 40 + k] = __float2half(whh[i]);
    }
    if (t < 96) { s_bi[t] = bih[t]; s_bh[t] = bhh[t]; }
    if (t >= 128 && t < 160) s_cb[t - 128] = convb[t - 128];
    __syncthreads();

    int w = t >> 5, lane = t & 31;
    int wb = blockIdx.x * 128 + w * 16;
    __half* sx = (__half*)s_buf[w];
    __half* sh = (__half*)(s_buf[w] + 1280);
    float*  so = (float*)s_buf[w];

    int r0 = lane >> 3, c4 = (lane & 7) * 4;
    float4 cb = *(float4*)&s_cb[c4];
    #pragma unroll
    for (int i = 0; i < 4; i++) {
        int row = r0 + i * 4;
        float4 av = *(const float4*)(g_agg + (size_t)(wb + row) * 32 + c4);
        *(__half2*)(sx + row * 40 + c4)     = __floats2half2_rn(fmaxf(av.x + cb.x, 0.f), fmaxf(av.y + cb.y, 0.f));
        *(__half2*)(sx + row * 40 + c4 + 2) = __floats2half2_rn(fmaxf(av.z + cb.z, 0.f), fmaxf(av.w + cb.w, 0.f));
        float4 hv = *(const float4*)(g_hidden + (size_t)(wb + row) * 32 + c4);
        *(__half2*)(sh + row * 40 + c4)     = __floats2half2_rn(hv.x, hv.y);
        *(__half2*)(sh + row * 40 + c4 + 2) = __floats2half2_rn(hv.z, hv.w);
    }
    __syncwarp();

    int g = lane >> 2, tg = lane & 3;
    unsigned af[2][4], hf[2][4];
    #pragma unroll
    for (int s = 0; s < 2; s++) {
        const __half* xr0 = sx + g * 40 + s * 16 + tg * 2;
        const __half* xr1 = sx + (g + 8) * 40 + s * 16 + tg * 2;
        af[s][0] = *(const unsigned*)(xr0);
        af[s][1] = *(const unsigned*)(xr1);
        af[s][2] = *(const unsigned*)(xr0 + 8);
        af[s][3] = *(const unsigned*)(xr1 + 8);
        const __half* hr0 = sh + g * 40 + s * 16 + tg * 2;
        const __half* hr1 = sh + (g + 8) * 40 + s * 16 + tg * 2;
        hf[s][0] = *(const unsigned*)(hr0);
        hf[s][1] = *(const unsigned*)(hr1);
        hf[s][2] = *(const unsigned*)(hr0 + 8);
        hf[s][3] = *(const unsigned*)(hr1 + 8);
    }
    __syncwarp();

    float* outp = last ? d_out : g_hidden;

    #pragma unroll
    for (int cg = 0; cg < 4; cg++) {
        float xr[4] = {0,0,0,0}, xz[4] = {0,0,0,0}, xn[4] = {0,0,0,0};
        float hr[4] = {0,0,0,0}, hz[4] = {0,0,0,0}, hn[4] = {0,0,0,0};
        #pragma unroll
        for (int s = 0; s < 2; s++) {
            const __half* p;
            unsigned b0, b1;
            p = s_wi + (cg * 8 + g) * 40 + s * 16 + tg * 2;
            b0 = *(const unsigned*)p; b1 = *(const unsigned*)(p + 8);
            MMA_F32(xr[0], xr[1], xr[2], xr[3], af[s][0], af[s][1], af[s][2], af[s][3], b0, b1);
            p = s_wi + (32 + cg * 8 + g) * 40 + s * 16 + tg * 2;
            b0 = *(const unsigned*)p; b1 = *(const unsigned*)(p + 8);
            MMA_F32(xz[0], xz[1], xz[2], xz[3], af[s][0], af[s][1], af[s][2], af[s][3], b0, b1);
            p = s_wi + (64 + cg * 8 + g) * 40 + s * 16 + tg * 2;
            b0 = *(const unsigned*)p; b1 = *(const unsigned*)(p + 8);
            MMA_F32(xn[0], xn[1], xn[2], xn[3], af[s][0], af[s][1], af[s][2], af[s][3], b0, b1);
            p = s_wh + (cg * 8 + g) * 40 + s * 16 + tg * 2;
            b0 = *(const unsigned*)p; b1 = *(const unsigned*)(p + 8);
            MMA_F32(hr[0], hr[1], hr[2], hr[3], hf[s][0], hf[s][1], hf[s][2], hf[s][3], b0, b1);
            p = s_wh + (32 + cg * 8 + g) * 40 + s * 16 + tg * 2;
            b0 = *(const unsigned*)p; b1 = *(const unsigned*)(p + 8);
            MMA_F32(hz[0], hz[1], hz[2], hz[3], hf[s][0], hf[s][1], hf[s][2], hf[s][3], b0, b1);
            p = s_wh + (64 + cg * 8 + g) * 40 + s * 16 + tg * 2;
            b0 = *(const unsigned*)p; b1 = *(const unsigned*)(p + 8);
            MMA_F32(hn[0], hn[1], hn[2], hn[3], hf[s][0], hf[s][1], hf[s][2], hf[s][3], b0, b1);
        }
        int u0 = cg * 8 + tg * 2;
        float2 bir = *(float2*)&s_bi[u0],      bhr = *(float2*)&s_bh[u0];
        float2 biz = *(float2*)&s_bi[32 + u0], bhz = *(float2*)&s_bh[32 + u0];
        float2 bin = *(float2*)&s_bi[64 + u0], bhn = *(float2*)&s_bh[64 + u0];
        #pragma unroll
        for (int jp = 0; jp < 2; jp++) {
            int rl = g + jp * 8;
            float2 hold = *(const float2*)(g_hidden + (size_t)(wb + rl) * 32 + u0);
            #pragma unroll
            for (int jj = 0; jj < 2; jj++) {
                int j = jp * 2 + jj;
                float bi_r = jj ? bir.y : bir.x, bh_r = jj ? bhr.y : bhr.x;
                float bi_z = jj ? biz.y : biz.x, bh_z = jj ? bhz.y : bhz.x;
                float bi_n = jj ? bin.y : bin.x, bh_n = jj ? bhn.y : bhn.x;
                float ho = jj ? hold.y : hold.x;
                float rv = sigmoidf_(xr[j] + hr[j] + bi_r + bh_r);
                float zv = sigmoidf_(xz[j] + hz[j] + bi_z + bh_z);
                float nv = tanhf(xn[j] + bi_n + rv * (hn[j] + bh_n));
                so[rl * 36 + u0 + jj] = (1.f - zv) * nv + zv * ho;
            }
        }
    }
    __syncwarp();

    float4 z4 = make_float4(0.f, 0.f, 0.f, 0.f);
    #pragma unroll
    for (int i = 0; i < 4; i++) {
        int row = r0 + i * 4;
        float4 val = *(float4*)(so + row * 36 + c4);
        *(float4*)(outp + (size_t)(wb + row) * 32 + c4) = val;
        *(float4*)(g_agg + (size_t)(wb + row) * 32 + c4) = z4;
    }
}

extern "C" void kernel_launch(void* const* d_in, const int* in_sizes, int n_in,
                              void* d_out, int out_size)
{
    const float* x     = (const float*)d_in[0];
    const float* rel   = (const float*)d_in[1];
    const float* pw1   = (const float*)d_in[2];
    const float* pb1   = (const float*)d_in[3];
    const float* pw2   = (const float*)d_in[4];
    const float* pb2   = (const float*)d_in[5];
    const float* ew1   = (const float*)d_in[6];
    const float* eb1   = (const float*)d_in[7];
    const float* ew2   = (const float*)d_in[8];
    const float* eb2   = (const float*)d_in[9];
    const float* convb = (const float*)d_in[10];
    const float* wih   = (const float*)d_in[11];
    const float* whh   = (const float*)d_in[12];
    const float* bih   = (const float*)d_in[13];
    const float* bhh   = (const float*)d_in[14];
    const int*   esrc  = (const int*)d_in[15];
    const int*   edst  = (const int*)d_in[16];
    float* out = (float*)d_out;

    cudaFuncSetAttribute(msgfused_kernel,
                         cudaFuncAttributeMaxDynamicSharedMemorySize, SM_TOTAL);

    proj_kernel<<<NB / 128, 128>>>(x, pw1, pb1, pw2, pb2);
    prep_b_kernel<<<4096 / 256, 256>>>(ew2, eb2);
    prep_a_kernel<<<N_EDGES / 256, 256>>>(rel, ew1, eb1);

    for (int s = 0; s < 3; s++) {
        msgfused_kernel<<<N_EDGES / 128, 256, SM_TOTAL>>>(esrc, edst);
        gru_kernel<<<NB / 128, 256>>>(wih, whh, bih, bhh, convb, out, s == 2 ? 1 : 0);
    }
}